// round 10
// baseline (speedup 1.0000x reference)
#include <cuda_runtime.h>
#include <cuda_bf16.h>
#include <cstdint>
#include <math.h>

#define T_DIM 4096
#define C_DIM 1024
#define NEG_INF_F (-1e30f)

// ============================================================================
// Scratch buffer (single device symbol). ~252 MB.
// ============================================================================
#define MB_ (1048576ull)
#define OFF_V    (32*MB_)          // fp32 v        16 MB
#define OFF_ATT  (48*MB_)          // fp32 att      64 MB
#define OFF_XH   (112*MB_)
#define OFF_XL   (120*MB_)
#define OFF_WTH  (128*MB_)
#define OFF_WTL  (134*MB_)
#define OFF_QH   (140*MB_)
#define OFF_QL   (148*MB_)
#define OFF_KH   (156*MB_)
#define OFF_KL   (164*MB_)
#define OFF_VTH  (172*MB_)
#define OFF_VTL  (180*MB_)
#define OFF_ATH  (188*MB_)
#define OFF_ATL  (220*MB_)
#define BUF_TOTAL (252*MB_)

__device__ __align__(1024) char g_buf[BUF_TOTAL];

// ============================================================================
// Baseline-PTX helpers (sm_80-class only: cp.async, ldmatrix, mma.sync)
// ============================================================================
__device__ __forceinline__ uint32_t smem_u32(const void* p) {
    uint32_t a;
    asm("{ .reg .u64 t; cvta.to.shared.u64 t, %1; cvt.u32.u64 %0, t; }" : "=r"(a) : "l"(p));
    return a;
}
__device__ __forceinline__ void cp16(uint32_t dst, const void* src) {
    asm volatile("cp.async.cg.shared.global [%0], [%1], 16;" :: "r"(dst), "l"(src));
}
#define CP_COMMIT() asm volatile("cp.async.commit_group;" ::: "memory")
#define CP_WAIT1()  asm volatile("cp.async.wait_group 1;" ::: "memory")

#define LDSM_X4(r, addr) \
    asm volatile("ldmatrix.sync.aligned.m8n8.x4.shared.b16 {%0,%1,%2,%3}, [%4];" \
        : "=r"((r)[0]), "=r"((r)[1]), "=r"((r)[2]), "=r"((r)[3]) : "r"(addr))

#define MMA16816(c, a, b0, b1) \
    asm volatile("mma.sync.aligned.m16n8k16.row.col.f32.bf16.bf16.f32 " \
        "{%0,%1,%2,%3}, {%4,%5,%6,%7}, {%8,%9}, {%0,%1,%2,%3};" \
        : "+f"((c)[0]), "+f"((c)[1]), "+f"((c)[2]), "+f"((c)[3]) \
        : "r"((a)[0]), "r"((a)[1]), "r"((a)[2]), "r"((a)[3]), "r"(b0), "r"(b1))

// ============================================================================
// Packed tile layout: operand [R rows, Ktot cols] K-major bf16 ->
// row-tiles of 128 x 64 cols, 16 KB each, SW128 swizzled, [R/128][Ktot/64].
// ============================================================================
#define TILE_BYTES 16384
#define NSTAGE 3
#define STAGE_BYTES (3 * TILE_BYTES)                      // A0 + A1 + B
#define SMEM_BYTES (1024 + NSTAGE * STAGE_BYTES)

// Split fp32 [R, KT*64] into hi/lo packed tiles (used for x only now).
__global__ void split_kernel(const float* __restrict__ in,
                             __nv_bfloat16* __restrict__ hi, __nv_bfloat16* __restrict__ lo,
                             int KT)
{
    const int kt = blockIdx.x, rt = blockIdx.y;
    const int ld = KT * 64;
    const float* src = in + (size_t)(rt * 128) * ld + kt * 64;
    char* hb = (char*)hi + (size_t)(rt * KT + kt) * TILE_BYTES;
    char* lb = (char*)lo + (size_t)(rt * KT + kt) * TILE_BYTES;
    for (int e = threadIdx.x; e < 8192; e += 256) {
        const int row = e >> 6, col = e & 63;
        const float v = src[row * ld + col];
        const __nv_bfloat16 h = __float2bfloat16(v);
        const __nv_bfloat16 l = __float2bfloat16(v - __bfloat162float(h));
        const int idx = row * 128 + col * 2;
        const int sw = idx ^ ((idx >> 3) & 0x70);
        *(__nv_bfloat16*)(hb + sw) = h;
        *(__nv_bfloat16*)(lb + sw) = l;
    }
}

// Transpose-split: fp32 [Kdim rows, N cols] -> operand [N rows, Kdim] tiles.
__global__ void tsplit_kernel(const float* __restrict__ in, int N,
                              __nv_bfloat16* __restrict__ hi, __nv_bfloat16* __restrict__ lo,
                              int KT)
{
    const int kt = blockIdx.x, nt = blockIdx.y;
    __shared__ float ts[64][133];
    const float* src = in + (size_t)(kt * 64) * N + nt * 128;
    for (int e = threadIdx.x; e < 8192; e += 256) {
        const int kk = e >> 7, nn = e & 127;
        ts[kk][nn] = src[kk * N + nn];
    }
    __syncthreads();
    char* hb = (char*)hi + (size_t)(nt * KT + kt) * TILE_BYTES;
    char* lb = (char*)lo + (size_t)(nt * KT + kt) * TILE_BYTES;
    for (int e = threadIdx.x; e < 8192; e += 256) {
        const int row = e >> 6, col = e & 63;
        const float v = ts[col][row];
        const __nv_bfloat16 h = __float2bfloat16(v);
        const __nv_bfloat16 l = __float2bfloat16(v - __bfloat162float(h));
        const int idx = row * 128 + col * 2;
        const int sw = idx ^ ((idx >> 3) & 0x70);
        *(__nv_bfloat16*)(hb + sw) = h;
        *(__nv_bfloat16*)(lb + sw) = l;
    }
}

// ============================================================================
// HMMA GEMM: D[256,128] fp32 = sum over 3 hi/lo combos of A * B^T (bf16).
// 8 warps (4m x 2n), warp tile 64x64, BK=64, 3-stage cp.async pipeline.
// MODE 0: QKV. cols<2048 -> q/k written as packed hi/lo tiles (+bias);
//         cols>=2048 -> v fp32 (+bias).
// MODE 1: QK -> att fp32 (scale + padding mask); only tiles with bx<=2by+1.
// MODE 2: PV -> out fp32; ktiles = 4*(by+1); by reversed.
// ============================================================================
template<int MODE>
__global__ __launch_bounds__(256, 1)
void mm_kernel(const char* __restrict__ Ah, const char* __restrict__ Al,
               const char* __restrict__ Bh, const char* __restrict__ Bl,
               int KT, float* __restrict__ fout,
               __nv_bfloat16* __restrict__ ph0, __nv_bfloat16* __restrict__ pl0,
               __nv_bfloat16* __restrict__ ph1, __nv_bfloat16* __restrict__ pl1,
               const float* __restrict__ bias, const int* __restrict__ n_padd_ptr)
{
    extern __shared__ char smem_raw[];
    const int tid = threadIdx.x;
    const int wid = tid >> 5, lane = tid & 31;
    const int wm = wid & 3, wn = wid >> 2;

    const int bx = blockIdx.x;
    int by = blockIdx.y;
    if (MODE == 1 && bx > 2 * by + 1) return;
    if (MODE == 2) by = gridDim.y - 1 - by;
    const int ktiles = (MODE == 2) ? 4 * (by + 1) : KT;
    const int total = 3 * ktiles;

    uint32_t sb = smem_u32(smem_raw);
    sb = (sb + 1023u) & ~1023u;

    const char* Asel[3] = {Ah, Ah, Al};
    const char* Bsel[3] = {Bh, Bl, Bh};

    // ldmatrix swizzled address bases. sw(idx) = rowpart + (colpart ^ xt),
    // xt = (rowpart>>3)&0x70, valid because colpart < 128.
    uint32_t abase[4], axt[4];
    #pragma unroll
    for (int mi = 0; mi < 4; mi++) {
        const int rowg = wm * 64 + mi * 16 + (lane & 15);       // 0..255
        const uint32_t rowpart = (uint32_t)(rowg & 127) * 128;
        abase[mi] = (uint32_t)(rowg >> 7) * TILE_BYTES + rowpart;
        axt[mi] = (rowpart >> 3) & 0x70;
    }
    const uint32_t cba = (uint32_t)(lane >> 4) << 4;            // k-half * 16B
    uint32_t bbase[4], bxt[4];
    #pragma unroll
    for (int nj = 0; nj < 4; nj++) {
        const int rowg = wn * 64 + nj * 16 + (lane & 7) + ((lane >> 4) << 3);
        const uint32_t rowpart = (uint32_t)rowg * 128;
        bbase[nj] = rowpart;
        bxt[nj] = (rowpart >> 3) & 0x70;
    }
    const uint32_t cbb = (uint32_t)((lane >> 3) & 1) << 4;

    float acc[4][8][4];
    #pragma unroll
    for (int mi = 0; mi < 4; mi++)
        #pragma unroll
        for (int ni = 0; ni < 8; ni++)
            #pragma unroll
            for (int e = 0; e < 4; e++) acc[mi][ni][e] = 0.f;

    auto issue = [&](int i) {
        const int c = i / ktiles, kt = i - c * ktiles;
        const char* A0 = Asel[c] + ((size_t)(2 * by) * KT + kt) * TILE_BYTES;
        const char* A1 = Asel[c] + ((size_t)(2 * by + 1) * KT + kt) * TILE_BYTES;
        const char* Bb = Bsel[c] + ((size_t)bx * KT + kt) * TILE_BYTES;
        const uint32_t st = sb + (i % NSTAGE) * STAGE_BYTES;
        #pragma unroll
        for (int w = 0; w < 4; w++) {
            const int o = w * 4096 + tid * 16;
            cp16(st + o, A0 + o);
            cp16(st + TILE_BYTES + o, A1 + o);
            cp16(st + 2 * TILE_BYTES + o, Bb + o);
        }
        CP_COMMIT();
    };

    issue(0);
    issue(1);

    for (int i = 0; i < total; i++) {
        CP_WAIT1();
        __syncthreads();
        const uint32_t st = sb + (i % NSTAGE) * STAGE_BYTES;
        const uint32_t stb = st + 2 * TILE_BYTES;

        #pragma unroll
        for (int ks = 0; ks < 4; ks++) {
            uint32_t afr[4][4], bfr[4][4];
            #pragma unroll
            for (int mi = 0; mi < 4; mi++)
                LDSM_X4(afr[mi], st + abase[mi] + (((uint32_t)(ks * 32) + cba) ^ axt[mi]));
            #pragma unroll
            for (int nj = 0; nj < 4; nj++)
                LDSM_X4(bfr[nj], stb + bbase[nj] + (((uint32_t)(ks * 32) + cbb) ^ bxt[nj]));
            #pragma unroll
            for (int mi = 0; mi < 4; mi++)
                #pragma unroll
                for (int ni = 0; ni < 8; ni++)
                    MMA16816(acc[mi][ni], afr[mi],
                             bfr[ni >> 1][(ni & 1) * 2],
                             bfr[ni >> 1][(ni & 1) * 2 + 1]);
        }

        if (i + 2 < total) issue(i + 2);
        else CP_COMMIT();           // empty group keeps wait accounting valid
    }

    // ---- epilogue ----
    const int qr = lane >> 2;
    const int qc = (lane & 3) * 2;

    #pragma unroll
    for (int mi = 0; mi < 4; mi++) {
        #pragma unroll
        for (int hf = 0; hf < 2; hf++) {
            const int r = by * 256 + wm * 64 + mi * 16 + qr + hf * 8;
            #pragma unroll
            for (int ni = 0; ni < 8; ni++) {
                const int cg = bx * 128 + wn * 64 + ni * 8 + qc;
                const float v0 = acc[mi][ni][hf * 2];
                const float v1 = acc[mi][ni][hf * 2 + 1];
                if (MODE == 0) {
                    const float f0 = v0 + bias[cg];
                    const float f1 = v1 + bias[cg + 1];
                    if (cg < 2048) {
                        // q (sec 0) / k (sec 1): write packed hi/lo tiles
                        const int sec = cg >> 10;
                        const int sc = cg & 1023;
                        char* H = (char*)(sec ? ph1 : ph0);
                        char* L = (char*)(sec ? pl1 : pl0);
                        const __nv_bfloat16 h0 = __float2bfloat16(f0);
                        const __nv_bfloat16 h1 = __float2bfloat16(f1);
                        const __nv_bfloat16 l0 = __float2bfloat16(f0 - __bfloat162float(h0));
                        const __nv_bfloat16 l1 = __float2bfloat16(f1 - __bfloat162float(h1));
                        const size_t tile = (size_t)((r >> 7) * 16 + (sc >> 6)) * TILE_BYTES;
                        const int idx = (r & 127) * 128 + (sc & 63) * 2;
                        const int sw = idx ^ ((idx >> 3) & 0x70);
                        *(uint32_t*)(H + tile + sw) =
                            ((uint32_t)__bfloat16_as_ushort(h1) << 16) | __bfloat16_as_ushort(h0);
                        *(uint32_t*)(L + tile + sw) =
                            ((uint32_t)__bfloat16_as_ushort(l1) << 16) | __bfloat16_as_ushort(l0);
                    } else {
                        float2 o = { f0, f1 };
                        *(float2*)(fout + (size_t)r * C_DIM + (cg - 2048)) = o;
                    }
                } else if (MODE == 1) {
                    const int np = *n_padd_ptr;
                    const float scale = 0.03125f;       // 1/sqrt(1024)
                    float2 o = { v0 * scale, v1 * scale };
                    if (r < np || cg     < np) o.x = NEG_INF_F;
                    if (r < np || cg + 1 < np) o.y = NEG_INF_F;
                    *(float2*)(fout + (size_t)r * T_DIM + cg) = o;
                } else {
                    float2 o = { v0, v1 };
                    *(float2*)(fout + (size_t)r * C_DIM + cg) = o;
                }
            }
        }
    }
}

// ============================================================================
// Single-pass softmax: one block per row; thread t owns cols [16t, 16t+16).
// Reads fp32 att once, writes packed hi/lo tiles directly, zero-filled to
// the 256-row-block boundary (PV's tile-aligned K range).
// ============================================================================
__global__ __launch_bounds__(256) void softmax_kernel(
    const float* __restrict__ att, char* __restrict__ ath, char* __restrict__ atl)
{
    const int r = blockIdx.x;
    const float* __restrict__ row = att + (size_t)r * T_DIM;
    const int n = r + 1;
    const int fill_end = ((r >> 8) + 1) << 8;
    const int tid = threadIdx.x;
    const int j0 = tid * 16;
    __shared__ float red[256];

    float x[16];
    #pragma unroll
    for (int g = 0; g < 4; g++) {
        const float4 t = *(const float4*)(row + j0 + g * 4);
        x[g*4+0] = t.x; x[g*4+1] = t.y; x[g*4+2] = t.z; x[g*4+3] = t.w;
    }
    // guard unwritten/garbage cols (j >= n)
    #pragma unroll
    for (int i = 0; i < 16; i++)
        if (j0 + i >= n) x[i] = NEG_INF_F;

    float m = x[0];
    #pragma unroll
    for (int i = 1; i < 16; i++) m = fmaxf(m, x[i]);
    red[tid] = m; __syncthreads();
    #pragma unroll
    for (int s = 128; s > 0; s >>= 1) {
        if (tid < s) red[tid] = fmaxf(red[tid], red[tid + s]);
        __syncthreads();
    }
    m = red[0];
    __syncthreads();

    float sum = 0.f;
    #pragma unroll
    for (int i = 0; i < 16; i++) {
        x[i] = __expf(x[i] - m);              // masked lanes underflow to 0
        sum += x[i];
    }
    red[tid] = sum; __syncthreads();
    #pragma unroll
    for (int s = 128; s > 0; s >>= 1) {
        if (tid < s) red[tid] += red[tid + s];
        __syncthreads();
    }
    const float inv = 1.0f / red[0];

    if (j0 < fill_end) {
        #pragma unroll
        for (int g = 0; g < 2; g++) {          // two 8-col groups = 16B each
            const int j = j0 + g * 8;
            uint4 uh, ul;
            uint32_t* ph = (uint32_t*)&uh;
            uint32_t* pl = (uint32_t*)&ul;
            #pragma unroll
            for (int p = 0; p < 4; p++) {
                const float p0 = x[g*8 + p*2]     * inv;
                const float p1 = x[g*8 + p*2 + 1] * inv;
                const __nv_bfloat16 h0 = __float2bfloat16(p0);
                const __nv_bfloat16 h1 = __float2bfloat16(p1);
                const __nv_bfloat16 l0 = __float2bfloat16(p0 - __bfloat162float(h0));
                const __nv_bfloat16 l1 = __float2bfloat16(p1 - __bfloat162float(h1));
                ph[p] = ((uint32_t)__bfloat16_as_ushort(h1) << 16) | __bfloat16_as_ushort(h0);
                pl[p] = ((uint32_t)__bfloat16_as_ushort(l1) << 16) | __bfloat16_as_ushort(l0);
            }
            const size_t tile = (size_t)((r >> 7) * 64 + (j >> 6)) * TILE_BYTES;
            const int idx = (r & 127) * 128 + (j & 63) * 2;
            const int sw = idx ^ ((idx >> 3) & 0x70);
            *(uint4*)(ath + tile + sw) = uh;
            *(uint4*)(atl + tile + sw) = ul;
        }
    }
}

// ============================================================================
extern "C" void kernel_launch(void* const* d_in, const int* in_sizes, int n_in,
                              void* d_out, int out_size)
{
    const float* x    = (const float*)d_in[0];   // [T, C]
    const float* W    = (const float*)d_in[1];   // [C, 3C]
    const float* bias = (const float*)d_in[2];   // [3C]
    const int* n_padd = (const int*)d_in[3];
    float* out = (float*)d_out;                  // [T, C]

    void* base = nullptr;
    cudaGetSymbolAddress(&base, g_buf);
    char* b = (char*)base;

    float* vf   = (float*)(b + OFF_V);
    float* att  = (float*)(b + OFF_ATT);
    __nv_bfloat16* xh  = (__nv_bfloat16*)(b + OFF_XH);
    __nv_bfloat16* xl  = (__nv_bfloat16*)(b + OFF_XL);
    __nv_bfloat16* wth = (__nv_bfloat16*)(b + OFF_WTH);
    __nv_bfloat16* wtl = (__nv_bfloat16*)(b + OFF_WTL);
    __nv_bfloat16* qh  = (__nv_bfloat16*)(b + OFF_QH);
    __nv_bfloat16* ql  = (__nv_bfloat16*)(b + OFF_QL);
    __nv_bfloat16* kh  = (__nv_bfloat16*)(b + OFF_KH);
    __nv_bfloat16* kl  = (__nv_bfloat16*)(b + OFF_KL);
    __nv_bfloat16* vth = (__nv_bfloat16*)(b + OFF_VTH);
    __nv_bfloat16* vtl = (__nv_bfloat16*)(b + OFF_VTL);
    __nv_bfloat16* ath = (__nv_bfloat16*)(b + OFF_ATH);
    __nv_bfloat16* atl = (__nv_bfloat16*)(b + OFF_ATL);

    cudaFuncSetAttribute(mm_kernel<0>, cudaFuncAttributeMaxDynamicSharedMemorySize, SMEM_BYTES);
    cudaFuncSetAttribute(mm_kernel<1>, cudaFuncAttributeMaxDynamicSharedMemorySize, SMEM_BYTES);
    cudaFuncSetAttribute(mm_kernel<2>, cudaFuncAttributeMaxDynamicSharedMemorySize, SMEM_BYTES);

    // 1) operand prep
    tsplit_kernel<<<dim3(16, 24), 256>>>(W, 3 * C_DIM, wth, wtl, 16);   // W^T [3072,1024]
    split_kernel <<<dim3(16, 32), 256>>>(x, xh, xl, 16);                // x   [4096,1024]

    // 2) QKV GEMM -> q/k packed hi/lo directly, v fp32
    mm_kernel<0><<<dim3(24, 16), 256, SMEM_BYTES>>>(
        (const char*)xh, (const char*)xl, (const char*)wth, (const char*)wtl,
        16, vf, qh, ql, kh, kl, bias, nullptr);

    // 3) v transpose-split
    tsplit_kernel<<<dim3(64, 8), 256>>>(vf, C_DIM, vth, vtl, 64);       // v^T [1024,4096]

    // 4) QK GEMM (lower tiles) -> att fp32 (scaled, padding-masked)
    mm_kernel<1><<<dim3(32, 16), 256, SMEM_BYTES>>>(
        (const char*)qh, (const char*)ql, (const char*)kh, (const char*)kl,
        16, att, nullptr, nullptr, nullptr, nullptr, nullptr, n_padd);

    // 5) softmax -> packed att hi/lo tiles (zero-filled to 256 boundary)
    softmax_kernel<<<T_DIM, 256>>>(att, (char*)ath, (char*)atl);

    // 6) PV GEMM -> y
    mm_kernel<2><<<dim3(8, 16), 256, SMEM_BYTES>>>(
        (const char*)ath, (const char*)atl, (const char*)vth, (const char*)vtl,
        64, out, nullptr, nullptr, nullptr, nullptr, nullptr, nullptr);
}

// round 11
// speedup vs baseline: 2.6470x; 2.6470x over previous
#include <cuda_runtime.h>
#include <cuda_fp16.h>
#include <cstdint>
#include <math.h>

#define T_DIM 4096
#define C_DIM 1024
#define NEG_INF_F (-1e30f)

// ============================================================================
// Scratch buffer (single device symbol).
// ============================================================================
#define MB_ (1048576ull)
#define OFF_V    (0ull)            // fp32 v       16 MB
#define OFF_ATT  (16*MB_)          // fp32 att     64 MB
#define OFF_XH   (80*MB_)          // x  packed     8 MB
#define OFF_WTH  (88*MB_)          // W^T packed    6 MB
#define OFF_QH   (96*MB_)          // q  packed     8 MB
#define OFF_KH   (104*MB_)         // k  packed     8 MB
#define OFF_VTH  (112*MB_)         // v^T packed    8 MB
#define OFF_ATH  (120*MB_)         // att packed   32 MB
#define BUF_TOTAL (152*MB_)

__device__ __align__(1024) char g_buf[BUF_TOTAL];

// ============================================================================
// Baseline-PTX helpers (sm_80-class only: cp.async, ldmatrix, mma.sync)
// ============================================================================
__device__ __forceinline__ uint32_t smem_u32(const void* p) {
    uint32_t a;
    asm("{ .reg .u64 t; cvta.to.shared.u64 t, %1; cvt.u32.u64 %0, t; }" : "=r"(a) : "l"(p));
    return a;
}
__device__ __forceinline__ void cp16(uint32_t dst, const void* src) {
    asm volatile("cp.async.cg.shared.global [%0], [%1], 16;" :: "r"(dst), "l"(src));
}
#define CP_COMMIT() asm volatile("cp.async.commit_group;" ::: "memory")
#define CP_WAIT1()  asm volatile("cp.async.wait_group 1;" ::: "memory")

#define LDSM_X4(r, addr) \
    asm volatile("ldmatrix.sync.aligned.m8n8.x4.shared.b16 {%0,%1,%2,%3}, [%4];" \
        : "=r"((r)[0]), "=r"((r)[1]), "=r"((r)[2]), "=r"((r)[3]) : "r"(addr))

// fp16 inputs, fp32 accumulators
#define MMA16816(c, a, b0, b1) \
    asm volatile("mma.sync.aligned.m16n8k16.row.col.f32.f16.f16.f32 " \
        "{%0,%1,%2,%3}, {%4,%5,%6,%7}, {%8,%9}, {%0,%1,%2,%3};" \
        : "+f"((c)[0]), "+f"((c)[1]), "+f"((c)[2]), "+f"((c)[3]) \
        : "r"((a)[0]), "r"((a)[1]), "r"((a)[2]), "r"((a)[3]), "r"(b0), "r"(b1))

// ============================================================================
// Packed tile layout: operand [R rows, Ktot cols] K-major fp16 ->
// row-tiles of 128 x 64 cols, 16 KB each, SW128 swizzled, [R/128][Ktot/64].
// ============================================================================
#define TILE_BYTES 16384
#define NSTAGE 3
#define STAGE_BYTES (3 * TILE_BYTES)                      // A0 + A1 + B
#define SMEM_BYTES (1024 + NSTAGE * STAGE_BYTES)

// Pack fp32 [R, KT*64] into fp16 swizzled tiles (x only).
__global__ void split_kernel(const float* __restrict__ in,
                             __half* __restrict__ dst, int KT)
{
    const int kt = blockIdx.x, rt = blockIdx.y;
    const int ld = KT * 64;
    const float* src = in + (size_t)(rt * 128) * ld + kt * 64;
    char* db = (char*)dst + (size_t)(rt * KT + kt) * TILE_BYTES;
    for (int e = threadIdx.x; e < 8192; e += 256) {
        const int row = e >> 6, col = e & 63;
        const int idx = row * 128 + col * 2;
        const int sw = idx ^ ((idx >> 3) & 0x70);
        *(__half*)(db + sw) = __float2half(src[row * ld + col]);
    }
}

// Transpose-pack: fp32 [Kdim rows, N cols] -> operand [N rows, Kdim] tiles.
__global__ void tsplit_kernel(const float* __restrict__ in, int N,
                              __half* __restrict__ dst, int KT)
{
    const int kt = blockIdx.x, nt = blockIdx.y;
    __shared__ float ts[64][133];
    const float* src = in + (size_t)(kt * 64) * N + nt * 128;
    for (int e = threadIdx.x; e < 8192; e += 256) {
        const int kk = e >> 7, nn = e & 127;
        ts[kk][nn] = src[kk * N + nn];
    }
    __syncthreads();
    char* db = (char*)dst + (size_t)(nt * KT + kt) * TILE_BYTES;
    for (int e = threadIdx.x; e < 8192; e += 256) {
        const int row = e >> 6, col = e & 63;
        const int idx = row * 128 + col * 2;
        const int sw = idx ^ ((idx >> 3) & 0x70);
        *(__half*)(db + sw) = __float2half(ts[col][row]);
    }
}

// ============================================================================
// HMMA GEMM: D[256,128] fp32 = A * B^T (fp16, fp32 accum), single pass.
// 8 warps (4m x 2n), warp tile 64x64, BK=64, 3-stage cp.async pipeline.
// MODE 0: QKV. cols<2048 -> q/k packed fp16 tiles (+bias); else v fp32 (+bias)
// MODE 1: QK -> att fp32 (scale + padding mask); only tiles with bx<=2by+1.
// MODE 2: PV -> out fp32; ktiles = 4*(by+1); by reversed.
// ============================================================================
template<int MODE>
__global__ __launch_bounds__(256, 1)
void mm_kernel(const char* __restrict__ Ap, const char* __restrict__ Bp,
               int KT, float* __restrict__ fout,
               __half* __restrict__ pq, __half* __restrict__ pk,
               const float* __restrict__ bias, const int* __restrict__ n_padd_ptr)
{
    extern __shared__ char smem_raw[];
    const int tid = threadIdx.x;
    const int wid = tid >> 5, lane = tid & 31;
    const int wm = wid & 3, wn = wid >> 2;

    const int bx = blockIdx.x;
    int by = blockIdx.y;
    if (MODE == 1 && bx > 2 * by + 1) return;
    if (MODE == 2) by = gridDim.y - 1 - by;
    const int total = (MODE == 2) ? 4 * (by + 1) : KT;

    uint32_t sb = smem_u32(smem_raw);
    sb = (sb + 1023u) & ~1023u;

    // ldmatrix swizzled address bases. sw(idx) = rowpart + (colpart ^ xt).
    uint32_t abase[4], axt[4];
    #pragma unroll
    for (int mi = 0; mi < 4; mi++) {
        const int rowg = wm * 64 + mi * 16 + (lane & 15);       // 0..255
        const uint32_t rowpart = (uint32_t)(rowg & 127) * 128;
        abase[mi] = (uint32_t)(rowg >> 7) * TILE_BYTES + rowpart;
        axt[mi] = (rowpart >> 3) & 0x70;
    }
    const uint32_t cba = (uint32_t)(lane >> 4) << 4;
    uint32_t bbase[4], bxt[4];
    #pragma unroll
    for (int nj = 0; nj < 4; nj++) {
        const int rowg = wn * 64 + nj * 16 + (lane & 7) + ((lane >> 4) << 3);
        const uint32_t rowpart = (uint32_t)rowg * 128;
        bbase[nj] = rowpart;
        bxt[nj] = (rowpart >> 3) & 0x70;
    }
    const uint32_t cbb = (uint32_t)((lane >> 3) & 1) << 4;

    float acc[4][8][4];
    #pragma unroll
    for (int mi = 0; mi < 4; mi++)
        #pragma unroll
        for (int ni = 0; ni < 8; ni++)
            #pragma unroll
            for (int e = 0; e < 4; e++) acc[mi][ni][e] = 0.f;

    const char* A0r = Ap + (size_t)(2 * by) * KT * TILE_BYTES;
    const char* A1r = Ap + (size_t)(2 * by + 1) * KT * TILE_BYTES;
    const char* Br  = Bp + (size_t)bx * KT * TILE_BYTES;

    auto issue = [&](int kt) {
        const uint32_t st = sb + (kt % NSTAGE) * STAGE_BYTES;
        const size_t toff = (size_t)kt * TILE_BYTES;
        #pragma unroll
        for (int w = 0; w < 4; w++) {
            const int o = w * 4096 + tid * 16;
            cp16(st + o, A0r + toff + o);
            cp16(st + TILE_BYTES + o, A1r + toff + o);
            cp16(st + 2 * TILE_BYTES + o, Br + toff + o);
        }
        CP_COMMIT();
    };

    issue(0);
    if (total > 1) issue(1);
    else CP_COMMIT();

    for (int i = 0; i < total; i++) {
        CP_WAIT1();
        __syncthreads();
        const uint32_t st = sb + (i % NSTAGE) * STAGE_BYTES;
        const uint32_t stb = st + 2 * TILE_BYTES;

        #pragma unroll
        for (int ks = 0; ks < 4; ks++) {
            uint32_t afr[4][4], bfr[4][4];
            #pragma unroll
            for (int mi = 0; mi < 4; mi++)
                LDSM_X4(afr[mi], st + abase[mi] + (((uint32_t)(ks * 32) + cba) ^ axt[mi]));
            #pragma unroll
            for (int nj = 0; nj < 4; nj++)
                LDSM_X4(bfr[nj], stb + bbase[nj] + (((uint32_t)(ks * 32) + cbb) ^ bxt[nj]));
            #pragma unroll
            for (int mi = 0; mi < 4; mi++)
                #pragma unroll
                for (int ni = 0; ni < 8; ni++)
                    MMA16816(acc[mi][ni], afr[mi],
                             bfr[ni >> 1][(ni & 1) * 2],
                             bfr[ni >> 1][(ni & 1) * 2 + 1]);
        }

        if (i + 2 < total) issue(i + 2);
        else CP_COMMIT();           // empty group keeps wait accounting valid
    }

    // ---- epilogue ----
    const int qr = lane >> 2;
    const int qc = (lane & 3) * 2;

    #pragma unroll
    for (int mi = 0; mi < 4; mi++) {
        #pragma unroll
        for (int hf = 0; hf < 2; hf++) {
            const int r = by * 256 + wm * 64 + mi * 16 + qr + hf * 8;
            #pragma unroll
            for (int ni = 0; ni < 8; ni++) {
                const int cg = bx * 128 + wn * 64 + ni * 8 + qc;
                const float v0 = acc[mi][ni][hf * 2];
                const float v1 = acc[mi][ni][hf * 2 + 1];
                if (MODE == 0) {
                    const float f0 = v0 + bias[cg];
                    const float f1 = v1 + bias[cg + 1];
                    if (cg < 2048) {
                        // q (sec 0) / k (sec 1): packed fp16 swizzled tiles
                        const int sec = cg >> 10;
                        const int sc = cg & 1023;
                        char* D = (char*)(sec ? pk : pq);
                        const __half h0 = __float2half(f0);
                        const __half h1 = __float2half(f1);
                        const size_t tile = (size_t)((r >> 7) * 16 + (sc >> 6)) * TILE_BYTES;
                        const int idx = (r & 127) * 128 + (sc & 63) * 2;
                        const int sw = idx ^ ((idx >> 3) & 0x70);
                        *(uint32_t*)(D + tile + sw) =
                            ((uint32_t)__half_as_ushort(h1) << 16) | __half_as_ushort(h0);
                    } else {
                        float2 o = { f0, f1 };
                        *(float2*)(fout + (size_t)r * C_DIM + (cg - 2048)) = o;
                    }
                } else if (MODE == 1) {
                    const int np = *n_padd_ptr;
                    const float scale = 0.03125f;       // 1/sqrt(1024)
                    float2 o = { v0 * scale, v1 * scale };
                    if (r < np || cg     < np) o.x = NEG_INF_F;
                    if (r < np || cg + 1 < np) o.y = NEG_INF_F;
                    *(float2*)(fout + (size_t)r * T_DIM + cg) = o;
                } else {
                    float2 o = { v0, v1 };
                    *(float2*)(fout + (size_t)r * C_DIM + cg) = o;
                }
            }
        }
    }
}

// ============================================================================
// Single-pass softmax: one block per row; thread t owns cols [16t, 16t+16).
// Reads fp32 att once, writes packed fp16 tiles, zero-filled to the
// 256-row-block boundary (PV's tile-aligned K range).
// ============================================================================
__global__ __launch_bounds__(256) void softmax_kernel(
    const float* __restrict__ att, char* __restrict__ ath)
{
    const int r = blockIdx.x;
    const float* __restrict__ row = att + (size_t)r * T_DIM;
    const int n = r + 1;
    const int fill_end = ((r >> 8) + 1) << 8;
    const int tid = threadIdx.x;
    const int j0 = tid * 16;
    __shared__ float red[256];

    float x[16];
    #pragma unroll
    for (int g = 0; g < 4; g++) {
        const float4 t = *(const float4*)(row + j0 + g * 4);
        x[g*4+0] = t.x; x[g*4+1] = t.y; x[g*4+2] = t.z; x[g*4+3] = t.w;
    }
    #pragma unroll
    for (int i = 0; i < 16; i++)
        if (j0 + i >= n) x[i] = NEG_INF_F;     // unwritten cols

    float m = x[0];
    #pragma unroll
    for (int i = 1; i < 16; i++) m = fmaxf(m, x[i]);
    red[tid] = m; __syncthreads();
    #pragma unroll
    for (int s = 128; s > 0; s >>= 1) {
        if (tid < s) red[tid] = fmaxf(red[tid], red[tid + s]);
        __syncthreads();
    }
    m = red[0];
    __syncthreads();

    float sum = 0.f;
    #pragma unroll
    for (int i = 0; i < 16; i++) {
        x[i] = __expf(x[i] - m);
        sum += x[i];
    }
    red[tid] = sum; __syncthreads();
    #pragma unroll
    for (int s = 128; s > 0; s >>= 1) {
        if (tid < s) red[tid] += red[tid + s];
        __syncthreads();
    }
    const float inv = 1.0f / red[0];

    if (j0 < fill_end) {
        #pragma unroll
        for (int g = 0; g < 2; g++) {          // two 8-col groups = 16B each
            const int j = j0 + g * 8;
            uint4 uh;
            uint32_t* ph = (uint32_t*)&uh;
            #pragma unroll
            for (int p = 0; p < 4; p++) {
                const __half h0 = __float2half(x[g*8 + p*2]     * inv);
                const __half h1 = __float2half(x[g*8 + p*2 + 1] * inv);
                ph[p] = ((uint32_t)__half_as_ushort(h1) << 16) | __half_as_ushort(h0);
            }
            const size_t tile = (size_t)((r >> 7) * 64 + (j >> 6)) * TILE_BYTES;
            const int idx = (r & 127) * 128 + (j & 63) * 2;
            const int sw = idx ^ ((idx >> 3) & 0x70);
            *(uint4*)(ath + tile + sw) = uh;
        }
    }
}

// ============================================================================
extern "C" void kernel_launch(void* const* d_in, const int* in_sizes, int n_in,
                              void* d_out, int out_size)
{
    const float* x    = (const float*)d_in[0];   // [T, C]
    const float* W    = (const float*)d_in[1];   // [C, 3C]
    const float* bias = (const float*)d_in[2];   // [3C]
    const int* n_padd = (const int*)d_in[3];
    float* out = (float*)d_out;                  // [T, C]

    void* base = nullptr;
    cudaGetSymbolAddress(&base, g_buf);
    char* b = (char*)base;

    float* vf   = (float*)(b + OFF_V);
    float* att  = (float*)(b + OFF_ATT);
    __half* xh  = (__half*)(b + OFF_XH);
    __half* wth = (__half*)(b + OFF_WTH);
    __half* qh  = (__half*)(b + OFF_QH);
    __half* kh  = (__half*)(b + OFF_KH);
    __half* vth = (__half*)(b + OFF_VTH);
    __half* ath = (__half*)(b + OFF_ATH);

    cudaFuncSetAttribute(mm_kernel<0>, cudaFuncAttributeMaxDynamicSharedMemorySize, SMEM_BYTES);
    cudaFuncSetAttribute(mm_kernel<1>, cudaFuncAttributeMaxDynamicSharedMemorySize, SMEM_BYTES);
    cudaFuncSetAttribute(mm_kernel<2>, cudaFuncAttributeMaxDynamicSharedMemorySize, SMEM_BYTES);

    // 1) operand prep
    tsplit_kernel<<<dim3(16, 24), 256>>>(W, 3 * C_DIM, wth, 16);   // W^T [3072,1024]
    split_kernel <<<dim3(16, 32), 256>>>(x, xh, 16);               // x   [4096,1024]

    // 2) QKV GEMM -> q/k packed fp16 directly, v fp32
    mm_kernel<0><<<dim3(24, 16), 256, SMEM_BYTES>>>(
        (const char*)xh, (const char*)wth, 16, vf, qh, kh, bias, nullptr);

    // 3) v transpose-pack
    tsplit_kernel<<<dim3(64, 8), 256>>>(vf, C_DIM, vth, 64);       // v^T [1024,4096]

    // 4) QK GEMM (lower tiles) -> att fp32 (scaled, padding-masked)
    mm_kernel<1><<<dim3(32, 16), 256, SMEM_BYTES>>>(
        (const char*)qh, (const char*)kh, 16, att, nullptr, nullptr, nullptr, n_padd);

    // 5) softmax -> packed att fp16 tiles (zero-filled to 256 boundary)
    softmax_kernel<<<T_DIM, 256>>>(att, (char*)ath);

    // 6) PV GEMM -> y
    mm_kernel<2><<<dim3(8, 16), 256, SMEM_BYTES>>>(
        (const char*)ath, (const char*)vth, 64, out, nullptr, nullptr, nullptr, nullptr);
}

// round 12
// speedup vs baseline: 2.8974x; 1.0946x over previous
#include <cuda_runtime.h>
#include <cuda_fp16.h>
#include <cstdint>
#include <math.h>

#define T_DIM 4096
#define C_DIM 1024
#define NEG_INF_F (-1e30f)

// ============================================================================
// Scratch buffer (single device symbol). 136 MB.
// ============================================================================
#define MB_ (1048576ull)
#define OFF_ATT  (0ull)            // fp32 att     64 MB
#define OFF_XH   (64*MB_)          // x  packed     8 MB
#define OFF_WTH  (72*MB_)          // W^T packed    6 MB
#define OFF_QH   (80*MB_)          // q  packed     8 MB
#define OFF_KH   (88*MB_)          // k  packed     8 MB
#define OFF_VTH  (96*MB_)          // v^T packed    8 MB
#define OFF_ATH  (104*MB_)         // att packed   32 MB
#define BUF_TOTAL (136*MB_)

__device__ __align__(1024) char g_buf[BUF_TOTAL];

// ============================================================================
// Baseline-PTX helpers (sm_80-class only: cp.async, ldmatrix, mma.sync)
// ============================================================================
__device__ __forceinline__ uint32_t smem_u32(const void* p) {
    uint32_t a;
    asm("{ .reg .u64 t; cvta.to.shared.u64 t, %1; cvt.u32.u64 %0, t; }" : "=r"(a) : "l"(p));
    return a;
}
__device__ __forceinline__ void cp16(uint32_t dst, const void* src) {
    asm volatile("cp.async.cg.shared.global [%0], [%1], 16;" :: "r"(dst), "l"(src));
}
#define CP_COMMIT() asm volatile("cp.async.commit_group;" ::: "memory")
#define CP_WAIT1()  asm volatile("cp.async.wait_group 1;" ::: "memory")

#define LDSM_X4(r, addr) \
    asm volatile("ldmatrix.sync.aligned.m8n8.x4.shared.b16 {%0,%1,%2,%3}, [%4];" \
        : "=r"((r)[0]), "=r"((r)[1]), "=r"((r)[2]), "=r"((r)[3]) : "r"(addr))

// fp16 inputs, fp32 accumulators
#define MMA16816(c, a, b0, b1) \
    asm volatile("mma.sync.aligned.m16n8k16.row.col.f32.f16.f16.f32 " \
        "{%0,%1,%2,%3}, {%4,%5,%6,%7}, {%8,%9}, {%0,%1,%2,%3};" \
        : "+f"((c)[0]), "+f"((c)[1]), "+f"((c)[2]), "+f"((c)[3]) \
        : "r"((a)[0]), "r"((a)[1]), "r"((a)[2]), "r"((a)[3]), "r"(b0), "r"(b1))

// ============================================================================
// Packed tile layout: operand [R rows, Ktot cols] K-major fp16 ->
// row-tiles of 128 x 64 cols, 16 KB each, SW128 swizzled, [R/128][Ktot/64].
// ============================================================================
#define TILE_BYTES 16384
#define NSTAGE 3
#define STAGE_BYTES (2 * TILE_BYTES)                      // A + B
#define SMEM_BYTES (1024 + NSTAGE * STAGE_BYTES)

// Pack fp32 [R, KT*64] into fp16 swizzled tiles (x only).
__global__ void split_kernel(const float* __restrict__ in,
                             __half* __restrict__ dst, int KT)
{
    const int kt = blockIdx.x, rt = blockIdx.y;
    const int ld = KT * 64;
    const float* src = in + (size_t)(rt * 128) * ld + kt * 64;
    char* db = (char*)dst + (size_t)(rt * KT + kt) * TILE_BYTES;
    for (int e = threadIdx.x; e < 8192; e += 256) {
        const int row = e >> 6, col = e & 63;
        const int idx = row * 128 + col * 2;
        const int sw = idx ^ ((idx >> 3) & 0x70);
        *(__half*)(db + sw) = __float2half(src[row * ld + col]);
    }
}

// Transpose-pack: fp32 [Kdim rows, N cols] -> operand [N rows, Kdim] tiles (W only).
__global__ void tsplit_kernel(const float* __restrict__ in, int N,
                              __half* __restrict__ dst, int KT)
{
    const int kt = blockIdx.x, nt = blockIdx.y;
    __shared__ float ts[64][133];
    const float* src = in + (size_t)(kt * 64) * N + nt * 128;
    for (int e = threadIdx.x; e < 8192; e += 256) {
        const int kk = e >> 7, nn = e & 127;
        ts[kk][nn] = src[kk * N + nn];
    }
    __syncthreads();
    char* db = (char*)dst + (size_t)(nt * KT + kt) * TILE_BYTES;
    for (int e = threadIdx.x; e < 8192; e += 256) {
        const int row = e >> 6, col = e & 63;
        const int idx = row * 128 + col * 2;
        const int sw = idx ^ ((idx >> 3) & 0x70);
        *(__half*)(db + sw) = __float2half(ts[col][row]);
    }
}

// ============================================================================
// HMMA GEMM: D[128,128] fp32 = A * B^T (fp16, fp32 accum), single pass.
// 8 warps (4m x 2n), warp tile 32x64, BK=64, 3-stage cp.async pipeline.
// MODE 0: QKV. cols<2048 -> q/k packed tiles (+bias); cols>=2048 -> v^T
//         packed tiles (+bias), written transposed.
// MODE 1: QK -> att fp32 (scale + padding mask); only tiles with bx<=by.
// MODE 2: PV -> out fp32; ktiles = 2*(by+1); by reversed (heavy first).
// ============================================================================
template<int MODE>
__global__ __launch_bounds__(256, 1)
void mm_kernel(const char* __restrict__ Ap, const char* __restrict__ Bp,
               int KT, float* __restrict__ fout,
               __half* __restrict__ pq, __half* __restrict__ pk,
               __half* __restrict__ pvt,
               const float* __restrict__ bias, const int* __restrict__ n_padd_ptr)
{
    extern __shared__ char smem_raw[];
    const int tid = threadIdx.x;
    const int wid = tid >> 5, lane = tid & 31;
    const int wm = wid & 3, wn = wid >> 2;

    const int bx = blockIdx.x;
    int by = blockIdx.y;
    if (MODE == 1 && bx > by) return;
    if (MODE == 2) by = gridDim.y - 1 - by;
    const int total = (MODE == 2) ? 2 * (by + 1) : KT;

    uint32_t sb = smem_u32(smem_raw);
    sb = (sb + 1023u) & ~1023u;

    // ldmatrix swizzled per-lane offsets within a 16 KB tile (round-9 proven).
    uint32_t a_off[2][4], b_off[4][4];
    #pragma unroll
    for (int mi = 0; mi < 2; mi++)
        #pragma unroll
        for (int ks = 0; ks < 4; ks++) {
            const int row = wm * 32 + mi * 16 + (lane & 15);
            const int col = ks * 16 + ((lane >> 4) << 3);
            const int idx = row * 128 + col * 2;
            a_off[mi][ks] = idx ^ ((idx >> 3) & 0x70);
        }
    #pragma unroll
    for (int nj = 0; nj < 4; nj++)
        #pragma unroll
        for (int ks = 0; ks < 4; ks++) {
            const int row = wn * 64 + nj * 16 + (lane & 7) + ((lane >> 4) << 3);
            const int col = ks * 16 + (((lane >> 3) & 1) << 3);
            const int idx = row * 128 + col * 2;
            b_off[nj][ks] = idx ^ ((idx >> 3) & 0x70);
        }

    float acc[2][8][4];
    #pragma unroll
    for (int mi = 0; mi < 2; mi++)
        #pragma unroll
        for (int ni = 0; ni < 8; ni++)
            #pragma unroll
            for (int e = 0; e < 4; e++) acc[mi][ni][e] = 0.f;

    const char* Ar = Ap + (size_t)by * KT * TILE_BYTES;
    const char* Br = Bp + (size_t)bx * KT * TILE_BYTES;

    auto issue = [&](int kt) {
        const uint32_t st = sb + (kt % NSTAGE) * STAGE_BYTES;
        const size_t toff = (size_t)kt * TILE_BYTES;
        #pragma unroll
        for (int w = 0; w < 4; w++) {
            const int o = w * 4096 + tid * 16;
            cp16(st + o, Ar + toff + o);
            cp16(st + TILE_BYTES + o, Br + toff + o);
        }
        CP_COMMIT();
    };

    issue(0);
    if (total > 1) issue(1);
    else CP_COMMIT();

    for (int i = 0; i < total; i++) {
        CP_WAIT1();
        __syncthreads();
        const uint32_t st = sb + (i % NSTAGE) * STAGE_BYTES;
        const uint32_t stb = st + TILE_BYTES;

        #pragma unroll
        for (int ks = 0; ks < 4; ks++) {
            uint32_t afr[2][4], bfr[4][4];
            #pragma unroll
            for (int mi = 0; mi < 2; mi++) LDSM_X4(afr[mi], st + a_off[mi][ks]);
            #pragma unroll
            for (int nj = 0; nj < 4; nj++) LDSM_X4(bfr[nj], stb + b_off[nj][ks]);
            #pragma unroll
            for (int mi = 0; mi < 2; mi++)
                #pragma unroll
                for (int ni = 0; ni < 8; ni++)
                    MMA16816(acc[mi][ni], afr[mi],
                             bfr[ni >> 1][(ni & 1) * 2],
                             bfr[ni >> 1][(ni & 1) * 2 + 1]);
        }

        if (i + 2 < total) issue(i + 2);
        else CP_COMMIT();           // empty group keeps wait accounting valid
    }

    // ---- epilogue ----
    const int qr = lane >> 2;
    const int qc = (lane & 3) * 2;

    #pragma unroll
    for (int mi = 0; mi < 2; mi++) {
        #pragma unroll
        for (int hf = 0; hf < 2; hf++) {
            const int r = by * 128 + wm * 32 + mi * 16 + qr + hf * 8;
            #pragma unroll
            for (int ni = 0; ni < 8; ni++) {
                const int cg = bx * 128 + wn * 64 + ni * 8 + qc;
                const float v0 = acc[mi][ni][hf * 2];
                const float v1 = acc[mi][ni][hf * 2 + 1];
                if (MODE == 0) {
                    const float f0 = v0 + bias[cg];
                    const float f1 = v1 + bias[cg + 1];
                    if (cg < 2048) {
                        // q (sec 0) / k (sec 1): packed fp16 swizzled tiles
                        const int sec = cg >> 10;
                        const int sc = cg & 1023;
                        char* D = (char*)(sec ? pk : pq);
                        const __half h0 = __float2half(f0);
                        const __half h1 = __float2half(f1);
                        const size_t tile = (size_t)((r >> 7) * 16 + (sc >> 6)) * TILE_BYTES;
                        const int idx = (r & 127) * 128 + (sc & 63) * 2;
                        const int sw = idx ^ ((idx >> 3) & 0x70);
                        *(uint32_t*)(D + tile + sw) =
                            ((uint32_t)__half_as_ushort(h1) << 16) | __half_as_ushort(h0);
                    } else {
                        // v: write v^T packed tiles directly (transposed scatter)
                        const int sc = cg - 2048;                  // feature row
                        const size_t tile = (size_t)((sc >> 7) * 64 + (r >> 6)) * TILE_BYTES;
                        const int idx = (sc & 127) * 128 + (r & 63) * 2;
                        const int sw  = idx ^ ((idx >> 3) & 0x70);
                        const int idx2 = idx + 128;                // feature sc+1
                        const int sw2 = idx2 ^ ((idx2 >> 3) & 0x70);
                        *(__half*)((char*)pvt + tile + sw)  = __float2half(f0);
                        *(__half*)((char*)pvt + tile + sw2) = __float2half(f1);
                    }
                } else if (MODE == 1) {
                    const int np = *n_padd_ptr;
                    const float scale = 0.03125f;       // 1/sqrt(1024)
                    float2 o = { v0 * scale, v1 * scale };
                    if (r < np || cg     < np) o.x = NEG_INF_F;
                    if (r < np || cg + 1 < np) o.y = NEG_INF_F;
                    *(float2*)(fout + (size_t)r * T_DIM + cg) = o;
                } else {
                    float2 o = { v0, v1 };
                    *(float2*)(fout + (size_t)r * C_DIM + cg) = o;
                }
            }
        }
    }
}

// ============================================================================
// Single-pass softmax: one block per row; thread t owns cols [16t, 16t+16).
// Reads fp32 att once, writes packed fp16 tiles, zero-filled to the
// 128-row-block boundary (PV's tile-aligned K range).
// ============================================================================
__global__ __launch_bounds__(256) void softmax_kernel(
    const float* __restrict__ att, char* __restrict__ ath)
{
    const int r = blockIdx.x;
    const float* __restrict__ row = att + (size_t)r * T_DIM;
    const int n = r + 1;
    const int fill_end = ((r >> 7) + 1) << 7;
    const int tid = threadIdx.x;
    const int j0 = tid * 16;
    __shared__ float red[256];

    float x[16];
    #pragma unroll
    for (int g = 0; g < 4; g++) {
        const float4 t = *(const float4*)(row + j0 + g * 4);
        x[g*4+0] = t.x; x[g*4+1] = t.y; x[g*4+2] = t.z; x[g*4+3] = t.w;
    }
    #pragma unroll
    for (int i = 0; i < 16; i++)
        if (j0 + i >= n) x[i] = NEG_INF_F;     // unwritten cols

    float m = x[0];
    #pragma unroll
    for (int i = 1; i < 16; i++) m = fmaxf(m, x[i]);
    red[tid] = m; __syncthreads();
    #pragma unroll
    for (int s = 128; s > 0; s >>= 1) {
        if (tid < s) red[tid] = fmaxf(red[tid], red[tid + s]);
        __syncthreads();
    }
    m = red[0];
    __syncthreads();

    float sum = 0.f;
    #pragma unroll
    for (int i = 0; i < 16; i++) {
        x[i] = __expf(x[i] - m);
        sum += x[i];
    }
    red[tid] = sum; __syncthreads();
    #pragma unroll
    for (int s = 128; s > 0; s >>= 1) {
        if (tid < s) red[tid] += red[tid + s];
        __syncthreads();
    }
    const float inv = 1.0f / red[0];

    if (j0 < fill_end) {
        #pragma unroll
        for (int g = 0; g < 2; g++) {          // two 8-col groups = 16B each
            const int j = j0 + g * 8;
            uint4 uh;
            uint32_t* ph = (uint32_t*)&uh;
            #pragma unroll
            for (int p = 0; p < 4; p++) {
                const __half h0 = __float2half(x[g*8 + p*2]     * inv);
                const __half h1 = __float2half(x[g*8 + p*2 + 1] * inv);
                ph[p] = ((uint32_t)__half_as_ushort(h1) << 16) | __half_as_ushort(h0);
            }
            const size_t tile = (size_t)((r >> 7) * 64 + (j >> 6)) * TILE_BYTES;
            const int idx = (r & 127) * 128 + (j & 63) * 2;
            const int sw = idx ^ ((idx >> 3) & 0x70);
            *(uint4*)(ath + tile + sw) = uh;
        }
    }
}

// ============================================================================
extern "C" void kernel_launch(void* const* d_in, const int* in_sizes, int n_in,
                              void* d_out, int out_size)
{
    const float* x    = (const float*)d_in[0];   // [T, C]
    const float* W    = (const float*)d_in[1];   // [C, 3C]
    const float* bias = (const float*)d_in[2];   // [3C]
    const int* n_padd = (const int*)d_in[3];
    float* out = (float*)d_out;                  // [T, C]

    void* base = nullptr;
    cudaGetSymbolAddress(&base, g_buf);
    char* b = (char*)base;

    float* att  = (float*)(b + OFF_ATT);
    __half* xh  = (__half*)(b + OFF_XH);
    __half* wth = (__half*)(b + OFF_WTH);
    __half* qh  = (__half*)(b + OFF_QH);
    __half* kh  = (__half*)(b + OFF_KH);
    __half* vth = (__half*)(b + OFF_VTH);
    __half* ath = (__half*)(b + OFF_ATH);

    cudaFuncSetAttribute(mm_kernel<0>, cudaFuncAttributeMaxDynamicSharedMemorySize, SMEM_BYTES);
    cudaFuncSetAttribute(mm_kernel<1>, cudaFuncAttributeMaxDynamicSharedMemorySize, SMEM_BYTES);
    cudaFuncSetAttribute(mm_kernel<2>, cudaFuncAttributeMaxDynamicSharedMemorySize, SMEM_BYTES);

    // 1) operand prep
    tsplit_kernel<<<dim3(16, 24), 256>>>(W, 3 * C_DIM, wth, 16);   // W^T [3072,1024]
    split_kernel <<<dim3(16, 32), 256>>>(x, xh, 16);               // x   [4096,1024]

    // 2) QKV GEMM -> q/k packed fp16, v^T packed fp16 (transposed in epilogue)
    mm_kernel<0><<<dim3(24, 32), 256, SMEM_BYTES>>>(
        (const char*)xh, (const char*)wth, 16, nullptr, qh, kh, vth, bias, nullptr);

    // 3) QK GEMM (lower tiles) -> att fp32 (scaled, padding-masked)
    mm_kernel<1><<<dim3(32, 32), 256, SMEM_BYTES>>>(
        (const char*)qh, (const char*)kh, 16, att,
        nullptr, nullptr, nullptr, nullptr, n_padd);

    // 4) softmax -> packed att fp16 tiles (zero-filled to 128 boundary)
    softmax_kernel<<<T_DIM, 256>>>(att, (char*)ath);

    // 5) PV GEMM -> y
    mm_kernel<2><<<dim3(8, 32), 256, SMEM_BYTES>>>(
        (const char*)ath, (const char*)vth, 64, out,
        nullptr, nullptr, nullptr, nullptr, nullptr);
}

// round 13
// speedup vs baseline: 2.9782x; 1.0279x over previous
#include <cuda_runtime.h>
#include <cuda_fp16.h>
#include <cstdint>
#include <math.h>

#define T_DIM 4096
#define C_DIM 1024
#define NEG_INF_F (-1e30f)

// ============================================================================
// Scratch buffer (single device symbol). 136 MB.
// ============================================================================
#define MB_ (1048576ull)
#define OFF_ATT  (0ull)            // fp32 att     64 MB
#define OFF_XH   (64*MB_)          // x  packed     8 MB
#define OFF_WTH  (72*MB_)          // W^T packed    6 MB
#define OFF_QH   (80*MB_)          // q  packed     8 MB
#define OFF_KH   (88*MB_)          // k  packed     8 MB
#define OFF_VTH  (96*MB_)          // v^T packed    8 MB
#define OFF_ATH  (104*MB_)         // att packed   32 MB
#define BUF_TOTAL (136*MB_)

__device__ __align__(1024) char g_buf[BUF_TOTAL];

// ============================================================================
// Baseline-PTX helpers (sm_80-class only: cp.async, ldmatrix, mma.sync)
// ============================================================================
__device__ __forceinline__ uint32_t smem_u32(const void* p) {
    uint32_t a;
    asm("{ .reg .u64 t; cvta.to.shared.u64 t, %1; cvt.u32.u64 %0, t; }" : "=r"(a) : "l"(p));
    return a;
}
__device__ __forceinline__ void cp16(uint32_t dst, const void* src) {
    asm volatile("cp.async.cg.shared.global [%0], [%1], 16;" :: "r"(dst), "l"(src));
}
#define CP_COMMIT() asm volatile("cp.async.commit_group;" ::: "memory")
#define CP_WAIT1()  asm volatile("cp.async.wait_group 1;" ::: "memory")

#define LDSM_X4(r, addr) \
    asm volatile("ldmatrix.sync.aligned.m8n8.x4.shared.b16 {%0,%1,%2,%3}, [%4];" \
        : "=r"((r)[0]), "=r"((r)[1]), "=r"((r)[2]), "=r"((r)[3]) : "r"(addr))

// fp16 inputs, fp32 accumulators
#define MMA16816(c, a, b0, b1) \
    asm volatile("mma.sync.aligned.m16n8k16.row.col.f32.f16.f16.f32 " \
        "{%0,%1,%2,%3}, {%4,%5,%6,%7}, {%8,%9}, {%0,%1,%2,%3};" \
        : "+f"((c)[0]), "+f"((c)[1]), "+f"((c)[2]), "+f"((c)[3]) \
        : "r"((a)[0]), "r"((a)[1]), "r"((a)[2]), "r"((a)[3]), "r"(b0), "r"(b1))

// ============================================================================
// Packed tile layout: operand [R rows, Ktot cols] K-major fp16 ->
// row-tiles of 128 x 64 cols, 16 KB each, SW128 swizzled, [R/128][Ktot/64].
// ============================================================================
#define TILE_BYTES 16384
#define NSTAGE 3
#define SMEM_BYTES (1024 + NSTAGE * 2 * TILE_BYTES)   // worst case (BN=128)

// Pack fp32 [R, KT*64] into fp16 swizzled tiles (x only).
__global__ void split_kernel(const float* __restrict__ in,
                             __half* __restrict__ dst, int KT)
{
    const int kt = blockIdx.x, rt = blockIdx.y;
    const int ld = KT * 64;
    const float* src = in + (size_t)(rt * 128) * ld + kt * 64;
    char* db = (char*)dst + (size_t)(rt * KT + kt) * TILE_BYTES;
    for (int e = threadIdx.x; e < 8192; e += 256) {
        const int row = e >> 6, col = e & 63;
        const int idx = row * 128 + col * 2;
        const int sw = idx ^ ((idx >> 3) & 0x70);
        *(__half*)(db + sw) = __float2half(src[row * ld + col]);
    }
}

// Transpose-pack: fp32 [Kdim rows, N cols] -> operand [N rows, Kdim] tiles (W only).
__global__ void tsplit_kernel(const float* __restrict__ in, int N,
                              __half* __restrict__ dst, int KT)
{
    const int kt = blockIdx.x, nt = blockIdx.y;
    __shared__ float ts[64][133];
    const float* src = in + (size_t)(kt * 64) * N + nt * 128;
    for (int e = threadIdx.x; e < 8192; e += 256) {
        const int kk = e >> 7, nn = e & 127;
        ts[kk][nn] = src[kk * N + nn];
    }
    __syncthreads();
    char* db = (char*)dst + (size_t)(nt * KT + kt) * TILE_BYTES;
    for (int e = threadIdx.x; e < 8192; e += 256) {
        const int row = e >> 6, col = e & 63;
        const int idx = row * 128 + col * 2;
        const int sw = idx ^ ((idx >> 3) & 0x70);
        *(__half*)(db + sw) = __float2half(ts[col][row]);
    }
}

// ============================================================================
// HMMA GEMM: D[128,BN] fp32 = A * B^T (fp16, fp32 accum), single pass.
// 8 warps (4m x 2n), BK=64, 3-stage cp.async pipeline.
// MODE 0: BN=64.  QKV: cols<2048 -> q/k packed tiles (+bias); cols>=2048 ->
//         v^T packed tiles (+bias), transposed scatter. grid (48, 32).
// MODE 1: BN=128. QK -> att fp32 (scale + padding mask); bx<=by. grid (32,32).
// MODE 2: BN=128. PV k-split2 -> atomicAdd into zeroed out. grid (8, 64);
//         y encodes (row-block, k-half), heavy blocks first.
// ============================================================================
template<int MODE>
__global__ __launch_bounds__(256, 1)
void mm_kernel(const char* __restrict__ Ap, const char* __restrict__ Bp,
               int KT, float* __restrict__ fout,
               __half* __restrict__ pq, __half* __restrict__ pk,
               __half* __restrict__ pvt,
               const float* __restrict__ bias, const int* __restrict__ n_padd_ptr)
{
    constexpr int BN     = (MODE == 0) ? 64 : 128;    // CTA N width
    constexpr int NI     = BN / 16;                   // MMAs per warp in n (8-wide)
    constexpr int NJB    = BN / 32;                   // B ldmatrix.x4 per ks
    constexpr int BBYTES = BN * 128;                  // B stage bytes
    constexpr int STAGE_BYTES = TILE_BYTES + BBYTES;

    extern __shared__ char smem_raw[];
    const int tid = threadIdx.x;
    const int wid = tid >> 5, lane = tid & 31;
    const int wm = wid & 3, wn = wid >> 2;

    const int bx = blockIdx.x;
    int by, total, koff;
    if (MODE == 1) {
        by = blockIdx.y;
        if (bx > by) return;
        total = KT; koff = 0;
    } else if (MODE == 2) {
        const int p = (int)(gridDim.y - 1 - blockIdx.y);  // heavy first
        by = p >> 1;                                      // row-block 0..31
        const int half = p & 1;
        total = by + 1;                                   // k-tiles this job
        koff = half * (by + 1);
    } else {
        by = blockIdx.y;
        total = KT; koff = 0;
    }

    uint32_t sb = smem_u32(smem_raw);
    sb = (sb + 1023u) & ~1023u;

    // ldmatrix swizzled per-lane offsets within a tile/block.
    uint32_t a_off[2][4], b_off[NJB][4];
    #pragma unroll
    for (int mi = 0; mi < 2; mi++)
        #pragma unroll
        for (int ks = 0; ks < 4; ks++) {
            const int row = wm * 32 + mi * 16 + (lane & 15);
            const int col = ks * 16 + ((lane >> 4) << 3);
            const int idx = row * 128 + col * 2;
            a_off[mi][ks] = idx ^ ((idx >> 3) & 0x70);
        }
    #pragma unroll
    for (int nj = 0; nj < NJB; nj++)
        #pragma unroll
        for (int ks = 0; ks < 4; ks++) {
            const int row = wn * (BN / 2) + nj * 16 + (lane & 7) + ((lane >> 4) << 3);
            const int col = ks * 16 + (((lane >> 3) & 1) << 3);
            const int idx = row * 128 + col * 2;
            b_off[nj][ks] = idx ^ ((idx >> 3) & 0x70);
        }

    float acc[2][NI][4];
    #pragma unroll
    for (int mi = 0; mi < 2; mi++)
        #pragma unroll
        for (int ni = 0; ni < NI; ni++)
            #pragma unroll
            for (int e = 0; e < 4; e++) acc[mi][ni][e] = 0.f;

    const char* Ar = Ap + ((size_t)by * KT + koff) * TILE_BYTES;
    const char* Br;
    if (MODE == 0) {
        // B block = 64-row half of a packed 128-row tile
        Br = Bp + (size_t)(bx >> 1) * KT * TILE_BYTES + (size_t)(bx & 1) * 8192;
    } else {
        Br = Bp + ((size_t)bx * KT + koff) * TILE_BYTES;
    }

    auto issue = [&](int kt) {
        const uint32_t st = sb + (kt % NSTAGE) * STAGE_BYTES;
        const size_t toff = (size_t)kt * TILE_BYTES;
        #pragma unroll
        for (int w = 0; w < 4; w++) {
            const int o = w * 4096 + tid * 16;
            cp16(st + o, Ar + toff + o);
        }
        #pragma unroll
        for (int w = 0; w < BBYTES / 4096; w++) {
            const int o = w * 4096 + tid * 16;
            cp16(st + TILE_BYTES + o, Br + toff + o);
        }
        CP_COMMIT();
    };

    issue(0);
    if (total > 1) issue(1);
    else CP_COMMIT();

    for (int i = 0; i < total; i++) {
        CP_WAIT1();
        __syncthreads();
        const uint32_t st = sb + (i % NSTAGE) * STAGE_BYTES;
        const uint32_t stb = st + TILE_BYTES;

        #pragma unroll
        for (int ks = 0; ks < 4; ks++) {
            uint32_t afr[2][4], bfr[NJB][4];
            #pragma unroll
            for (int mi = 0; mi < 2; mi++) LDSM_X4(afr[mi], st + a_off[mi][ks]);
            #pragma unroll
            for (int nj = 0; nj < NJB; nj++) LDSM_X4(bfr[nj], stb + b_off[nj][ks]);
            #pragma unroll
            for (int mi = 0; mi < 2; mi++)
                #pragma unroll
                for (int ni = 0; ni < NI; ni++)
                    MMA16816(acc[mi][ni], afr[mi],
                             bfr[ni >> 1][(ni & 1) * 2],
                             bfr[ni >> 1][(ni & 1) * 2 + 1]);
        }

        if (i + 2 < total) issue(i + 2);
        else CP_COMMIT();           // empty group keeps wait accounting valid
    }

    // ---- epilogue ----
    const int qr = lane >> 2;
    const int qc = (lane & 3) * 2;

    #pragma unroll
    for (int mi = 0; mi < 2; mi++) {
        #pragma unroll
        for (int hf = 0; hf < 2; hf++) {
            const int r = by * 128 + wm * 32 + mi * 16 + qr + hf * 8;
            #pragma unroll
            for (int ni = 0; ni < NI; ni++) {
                const int cg = bx * BN + wn * (BN / 2) + ni * 8 + qc;
                const float v0 = acc[mi][ni][hf * 2];
                const float v1 = acc[mi][ni][hf * 2 + 1];
                if (MODE == 0) {
                    const float f0 = v0 + bias[cg];
                    const float f1 = v1 + bias[cg + 1];
                    if (cg < 2048) {
                        // q (sec 0) / k (sec 1): packed fp16 swizzled tiles
                        const int sec = cg >> 10;
                        const int sc = cg & 1023;
                        char* D = (char*)(sec ? pk : pq);
                        const __half h0 = __float2half(f0);
                        const __half h1 = __float2half(f1);
                        const size_t tile = (size_t)((r >> 7) * 16 + (sc >> 6)) * TILE_BYTES;
                        const int idx = (r & 127) * 128 + (sc & 63) * 2;
                        const int sw = idx ^ ((idx >> 3) & 0x70);
                        *(uint32_t*)(D + tile + sw) =
                            ((uint32_t)__half_as_ushort(h1) << 16) | __half_as_ushort(h0);
                    } else {
                        // v: write v^T packed tiles directly (transposed scatter)
                        const int sc = cg - 2048;                  // feature row
                        const size_t tile = (size_t)((sc >> 7) * 64 + (r >> 6)) * TILE_BYTES;
                        const int idx = (sc & 127) * 128 + (r & 63) * 2;
                        const int sw  = idx ^ ((idx >> 3) & 0x70);
                        const int idx2 = idx + 128;                // feature sc+1
                        const int sw2 = idx2 ^ ((idx2 >> 3) & 0x70);
                        *(__half*)((char*)pvt + tile + sw)  = __float2half(f0);
                        *(__half*)((char*)pvt + tile + sw2) = __float2half(f1);
                    }
                } else if (MODE == 1) {
                    const int np = *n_padd_ptr;
                    const float scale = 0.03125f;       // 1/sqrt(1024)
                    float2 o = { v0 * scale, v1 * scale };
                    if (r < np || cg     < np) o.x = NEG_INF_F;
                    if (r < np || cg + 1 < np) o.y = NEG_INF_F;
                    *(float2*)(fout + (size_t)r * T_DIM + cg) = o;
                } else {
                    // PV k-split: accumulate both halves into zeroed out
                    atomicAdd(fout + (size_t)r * C_DIM + cg,     v0);
                    atomicAdd(fout + (size_t)r * C_DIM + cg + 1, v1);
                }
            }
        }
    }
}

// ============================================================================
// Single-pass softmax: one block per row; thread t owns cols [16t, 16t+16).
// Reads fp32 att once, writes packed fp16 tiles, zero-filled to the
// 128-row-block boundary (PV's tile-aligned K range).
// ============================================================================
__global__ __launch_bounds__(256) void softmax_kernel(
    const float* __restrict__ att, char* __restrict__ ath)
{
    const int r = blockIdx.x;
    const float* __restrict__ row = att + (size_t)r * T_DIM;
    const int n = r + 1;
    const int fill_end = ((r >> 7) + 1) << 7;
    const int tid = threadIdx.x;
    const int j0 = tid * 16;
    __shared__ float red[256];

    float x[16];
    #pragma unroll
    for (int g = 0; g < 4; g++) {
        const float4 t = *(const float4*)(row + j0 + g * 4);
        x[g*4+0] = t.x; x[g*4+1] = t.y; x[g*4+2] = t.z; x[g*4+3] = t.w;
    }
    #pragma unroll
    for (int i = 0; i < 16; i++)
        if (j0 + i >= n) x[i] = NEG_INF_F;     // unwritten cols

    float m = x[0];
    #pragma unroll
    for (int i = 1; i < 16; i++) m = fmaxf(m, x[i]);
    red[tid] = m; __syncthreads();
    #pragma unroll
    for (int s = 128; s > 0; s >>= 1) {
        if (tid < s) red[tid] = fmaxf(red[tid], red[tid + s]);
        __syncthreads();
    }
    m = red[0];
    __syncthreads();

    float sum = 0.f;
    #pragma unroll
    for (int i = 0; i < 16; i++) {
        x[i] = __expf(x[i] - m);
        sum += x[i];
    }
    red[tid] = sum; __syncthreads();
    #pragma unroll
    for (int s = 128; s > 0; s >>= 1) {
        if (tid < s) red[tid] += red[tid + s];
        __syncthreads();
    }
    const float inv = 1.0f / red[0];

    if (j0 < fill_end) {
        #pragma unroll
        for (int g = 0; g < 2; g++) {          // two 8-col groups = 16B each
            const int j = j0 + g * 8;
            uint4 uh;
            uint32_t* ph = (uint32_t*)&uh;
            #pragma unroll
            for (int p = 0; p < 4; p++) {
                const __half h0 = __float2half(x[g*8 + p*2]     * inv);
                const __half h1 = __float2half(x[g*8 + p*2 + 1] * inv);
                ph[p] = ((uint32_t)__half_as_ushort(h1) << 16) | __half_as_ushort(h0);
            }
            const size_t tile = (size_t)((r >> 7) * 64 + (j >> 6)) * TILE_BYTES;
            const int idx = (r & 127) * 128 + (j & 63) * 2;
            const int sw = idx ^ ((idx >> 3) & 0x70);
            *(uint4*)(ath + tile + sw) = uh;
        }
    }
}

// ============================================================================
extern "C" void kernel_launch(void* const* d_in, const int* in_sizes, int n_in,
                              void* d_out, int out_size)
{
    const float* x    = (const float*)d_in[0];   // [T, C]
    const float* W    = (const float*)d_in[1];   // [C, 3C]
    const float* bias = (const float*)d_in[2];   // [3C]
    const int* n_padd = (const int*)d_in[3];
    float* out = (float*)d_out;                  // [T, C]

    void* base = nullptr;
    cudaGetSymbolAddress(&base, g_buf);
    char* b = (char*)base;

    float* att  = (float*)(b + OFF_ATT);
    __half* xh  = (__half*)(b + OFF_XH);
    __half* wth = (__half*)(b + OFF_WTH);
    __half* qh  = (__half*)(b + OFF_QH);
    __half* kh  = (__half*)(b + OFF_KH);
    __half* vth = (__half*)(b + OFF_VTH);
    __half* ath = (__half*)(b + OFF_ATH);

    cudaFuncSetAttribute(mm_kernel<0>, cudaFuncAttributeMaxDynamicSharedMemorySize, SMEM_BYTES);
    cudaFuncSetAttribute(mm_kernel<1>, cudaFuncAttributeMaxDynamicSharedMemorySize, SMEM_BYTES);
    cudaFuncSetAttribute(mm_kernel<2>, cudaFuncAttributeMaxDynamicSharedMemorySize, SMEM_BYTES);

    // 0) zero out (PV accumulates atomically)
    cudaMemsetAsync(out, 0, (size_t)T_DIM * C_DIM * sizeof(float));

    // 1) operand prep
    tsplit_kernel<<<dim3(16, 24), 256>>>(W, 3 * C_DIM, wth, 16);   // W^T [3072,1024]
    split_kernel <<<dim3(16, 32), 256>>>(x, xh, 16);               // x   [4096,1024]

    // 2) QKV GEMM (N=64 tiles) -> q/k packed fp16, v^T packed fp16
    mm_kernel<0><<<dim3(48, 32), 256, SMEM_BYTES>>>(
        (const char*)xh, (const char*)wth, 16, nullptr, qh, kh, vth, bias, nullptr);

    // 3) QK GEMM (lower tiles) -> att fp32 (scaled, padding-masked)
    mm_kernel<1><<<dim3(32, 32), 256, SMEM_BYTES>>>(
        (const char*)qh, (const char*)kh, 16, att,
        nullptr, nullptr, nullptr, nullptr, n_padd);

    // 4) softmax -> packed att fp16 tiles (zero-filled to 128 boundary)
    softmax_kernel<<<T_DIM, 256>>>(att, (char*)ath);

    // 5) PV GEMM, k-split2 -> atomicAdd into out
    mm_kernel<2><<<dim3(8, 64), 256, SMEM_BYTES>>>(
        (const char*)ath, (const char*)vth, 64, out,
        nullptr, nullptr, nullptr, nullptr, nullptr);
}

// round 14
// speedup vs baseline: 2.9827x; 1.0015x over previous
#include <cuda_runtime.h>
#include <cuda_fp16.h>
#include <cstdint>
#include <math.h>

#define T_DIM 4096
#define C_DIM 1024
#define NEG_INF_F (-1e30f)

// ============================================================================
// Scratch buffer (single device symbol). 136 MB.
// ============================================================================
#define MB_ (1048576ull)
#define OFF_ATT  (0ull)            // fp32 att     64 MB
#define OFF_XH   (64*MB_)          // x  packed     8 MB
#define OFF_WTH  (72*MB_)          // W^T packed    6 MB
#define OFF_QH   (80*MB_)          // q  packed     8 MB
#define OFF_KH   (88*MB_)          // k  packed     8 MB
#define OFF_VTH  (96*MB_)          // v^T packed    8 MB
#define OFF_ATH  (104*MB_)         // att packed   32 MB
#define BUF_TOTAL (136*MB_)

__device__ __align__(1024) char g_buf[BUF_TOTAL];

// ============================================================================
// Baseline-PTX helpers (sm_80-class only: cp.async, ldmatrix, mma.sync)
// ============================================================================
__device__ __forceinline__ uint32_t smem_u32(const void* p) {
    uint32_t a;
    asm("{ .reg .u64 t; cvta.to.shared.u64 t, %1; cvt.u32.u64 %0, t; }" : "=r"(a) : "l"(p));
    return a;
}
__device__ __forceinline__ void cp16(uint32_t dst, const void* src) {
    asm volatile("cp.async.cg.shared.global [%0], [%1], 16;" :: "r"(dst), "l"(src));
}
#define CP_COMMIT() asm volatile("cp.async.commit_group;" ::: "memory")
#define CP_WAIT1()  asm volatile("cp.async.wait_group 1;" ::: "memory")

#define LDSM_X4(r, addr) \
    asm volatile("ldmatrix.sync.aligned.m8n8.x4.shared.b16 {%0,%1,%2,%3}, [%4];" \
        : "=r"((r)[0]), "=r"((r)[1]), "=r"((r)[2]), "=r"((r)[3]) : "r"(addr))

// fp16 inputs, fp32 accumulators
#define MMA16816(c, a, b0, b1) \
    asm volatile("mma.sync.aligned.m16n8k16.row.col.f32.f16.f16.f32 " \
        "{%0,%1,%2,%3}, {%4,%5,%6,%7}, {%8,%9}, {%0,%1,%2,%3};" \
        : "+f"((c)[0]), "+f"((c)[1]), "+f"((c)[2]), "+f"((c)[3]) \
        : "r"((a)[0]), "r"((a)[1]), "r"((a)[2]), "r"((a)[3]), "r"(b0), "r"(b1))

// ============================================================================
// Packed tile layout: operand [R rows, Ktot cols] K-major fp16 ->
// row-tiles of 128 x 64 cols, 16 KB each, SW128 swizzled, [R/128][Ktot/64].
// ============================================================================
#define TILE_BYTES 16384
#define NSTAGE 3
#define SMEM_BYTES (1024 + NSTAGE * 2 * TILE_BYTES)   // worst case (BN=128)

// Pack fp32 [R, KT*64] into fp16 swizzled tiles (x only).
__global__ void split_kernel(const float* __restrict__ in,
                             __half* __restrict__ dst, int KT)
{
    const int kt = blockIdx.x, rt = blockIdx.y;
    const int ld = KT * 64;
    const float* src = in + (size_t)(rt * 128) * ld + kt * 64;
    char* db = (char*)dst + (size_t)(rt * KT + kt) * TILE_BYTES;
    for (int e = threadIdx.x; e < 8192; e += 256) {
        const int row = e >> 6, col = e & 63;
        const int idx = row * 128 + col * 2;
        const int sw = idx ^ ((idx >> 3) & 0x70);
        *(__half*)(db + sw) = __float2half(src[row * ld + col]);
    }
}

// Transpose-pack: fp32 [Kdim rows, N cols] -> operand [N rows, Kdim] tiles (W only).
__global__ void tsplit_kernel(const float* __restrict__ in, int N,
                              __half* __restrict__ dst, int KT)
{
    const int kt = blockIdx.x, nt = blockIdx.y;
    __shared__ float ts[64][133];
    const float* src = in + (size_t)(kt * 64) * N + nt * 128;
    for (int e = threadIdx.x; e < 8192; e += 256) {
        const int kk = e >> 7, nn = e & 127;
        ts[kk][nn] = src[kk * N + nn];
    }
    __syncthreads();
    char* db = (char*)dst + (size_t)(nt * KT + kt) * TILE_BYTES;
    for (int e = threadIdx.x; e < 8192; e += 256) {
        const int row = e >> 6, col = e & 63;
        const int idx = row * 128 + col * 2;
        const int sw = idx ^ ((idx >> 3) & 0x70);
        *(__half*)(db + sw) = __float2half(ts[col][row]);
    }
}

// ============================================================================
// HMMA GEMM: D[128,BN] fp32 = A * B^T (fp16, fp32 accum), single pass.
// 8 warps (4m x 2n), BK=64, 3-stage cp.async pipeline.
// MODE 0: BN=64.  QKV: cols<2048 -> q/k packed tiles (+bias); cols>=2048 ->
//         v^T packed tiles (+bias), transposed scatter. grid (48, 32).
// MODE 1: BN=128. QK -> att fp32 (scale + padding mask); bx<=by. grid (32,32).
// MODE 2: BN=128. PV k-split2 -> atomicAdd into zeroed out. grid (8, 64);
//         y encodes (row-block, k-half), heavy blocks first.
// ============================================================================
template<int MODE>
__global__ __launch_bounds__(256, 1)
void mm_kernel(const char* __restrict__ Ap, const char* __restrict__ Bp,
               int KT, float* __restrict__ fout,
               __half* __restrict__ pq, __half* __restrict__ pk,
               __half* __restrict__ pvt,
               const float* __restrict__ bias, const int* __restrict__ n_padd_ptr)
{
    constexpr int BN     = (MODE == 0) ? 64 : 128;    // CTA N width
    constexpr int NI     = BN / 16;                   // MMAs per warp in n (8-wide)
    constexpr int NJB    = BN / 32;                   // B ldmatrix.x4 per ks
    constexpr int BBYTES = BN * 128;                  // B stage bytes
    constexpr int STAGE_BYTES = TILE_BYTES + BBYTES;

    extern __shared__ char smem_raw[];
    const int tid = threadIdx.x;
    const int wid = tid >> 5, lane = tid & 31;
    const int wm = wid & 3, wn = wid >> 2;

    const int bx = blockIdx.x;
    int by, total, koff;
    if (MODE == 1) {
        by = blockIdx.y;
        if (bx > by) return;
        total = KT; koff = 0;
    } else if (MODE == 2) {
        const int p = (int)(gridDim.y - 1 - blockIdx.y);  // heavy first
        by = p >> 1;                                      // row-block 0..31
        const int half = p & 1;
        total = by + 1;                                   // k-tiles this job
        koff = half * (by + 1);
    } else {
        by = blockIdx.y;
        total = KT; koff = 0;
    }

    uint32_t sb = smem_u32(smem_raw);
    sb = (sb + 1023u) & ~1023u;

    // ldmatrix swizzled per-lane offsets within a tile/block.
    uint32_t a_off[2][4], b_off[NJB][4];
    #pragma unroll
    for (int mi = 0; mi < 2; mi++)
        #pragma unroll
        for (int ks = 0; ks < 4; ks++) {
            const int row = wm * 32 + mi * 16 + (lane & 15);
            const int col = ks * 16 + ((lane >> 4) << 3);
            const int idx = row * 128 + col * 2;
            a_off[mi][ks] = idx ^ ((idx >> 3) & 0x70);
        }
    #pragma unroll
    for (int nj = 0; nj < NJB; nj++)
        #pragma unroll
        for (int ks = 0; ks < 4; ks++) {
            const int row = wn * (BN / 2) + nj * 16 + (lane & 7) + ((lane >> 4) << 3);
            const int col = ks * 16 + (((lane >> 3) & 1) << 3);
            const int idx = row * 128 + col * 2;
            b_off[nj][ks] = idx ^ ((idx >> 3) & 0x70);
        }

    float acc[2][NI][4];
    #pragma unroll
    for (int mi = 0; mi < 2; mi++)
        #pragma unroll
        for (int ni = 0; ni < NI; ni++)
            #pragma unroll
            for (int e = 0; e < 4; e++) acc[mi][ni][e] = 0.f;

    const char* Ar = Ap + ((size_t)by * KT + koff) * TILE_BYTES;
    const char* Br;
    if (MODE == 0) {
        // B block = 64-row half of a packed 128-row tile
        Br = Bp + (size_t)(bx >> 1) * KT * TILE_BYTES + (size_t)(bx & 1) * 8192;
    } else {
        Br = Bp + ((size_t)bx * KT + koff) * TILE_BYTES;
    }

    auto issue = [&](int kt) {
        const uint32_t st = sb + (kt % NSTAGE) * STAGE_BYTES;
        const size_t toff = (size_t)kt * TILE_BYTES;
        #pragma unroll
        for (int w = 0; w < 4; w++) {
            const int o = w * 4096 + tid * 16;
            cp16(st + o, Ar + toff + o);
        }
        #pragma unroll
        for (int w = 0; w < BBYTES / 4096; w++) {
            const int o = w * 4096 + tid * 16;
            cp16(st + TILE_BYTES + o, Br + toff + o);
        }
        CP_COMMIT();
    };

    issue(0);
    if (total > 1) issue(1);
    else CP_COMMIT();

    for (int i = 0; i < total; i++) {
        CP_WAIT1();
        __syncthreads();
        const uint32_t st = sb + (i % NSTAGE) * STAGE_BYTES;
        const uint32_t stb = st + TILE_BYTES;

        #pragma unroll
        for (int ks = 0; ks < 4; ks++) {
            uint32_t afr[2][4], bfr[NJB][4];
            #pragma unroll
            for (int mi = 0; mi < 2; mi++) LDSM_X4(afr[mi], st + a_off[mi][ks]);
            #pragma unroll
            for (int nj = 0; nj < NJB; nj++) LDSM_X4(bfr[nj], stb + b_off[nj][ks]);
            #pragma unroll
            for (int mi = 0; mi < 2; mi++)
                #pragma unroll
                for (int ni = 0; ni < NI; ni++)
                    MMA16816(acc[mi][ni], afr[mi],
                             bfr[ni >> 1][(ni & 1) * 2],
                             bfr[ni >> 1][(ni & 1) * 2 + 1]);
        }

        if (i + 2 < total) issue(i + 2);
        else CP_COMMIT();           // empty group keeps wait accounting valid
    }

    // ---- epilogue ----
    const int qr = lane >> 2;
    const int qc = (lane & 3) * 2;

    #pragma unroll
    for (int mi = 0; mi < 2; mi++) {
        #pragma unroll
        for (int hf = 0; hf < 2; hf++) {
            const int r = by * 128 + wm * 32 + mi * 16 + qr + hf * 8;
            #pragma unroll
            for (int ni = 0; ni < NI; ni++) {
                const int cg = bx * BN + wn * (BN / 2) + ni * 8 + qc;
                const float v0 = acc[mi][ni][hf * 2];
                const float v1 = acc[mi][ni][hf * 2 + 1];
                if (MODE == 0) {
                    const float f0 = v0 + bias[cg];
                    const float f1 = v1 + bias[cg + 1];
                    if (cg < 2048) {
                        // q (sec 0) / k (sec 1): packed fp16 swizzled tiles
                        const int sec = cg >> 10;
                        const int sc = cg & 1023;
                        char* D = (char*)(sec ? pk : pq);
                        const __half h0 = __float2half(f0);
                        const __half h1 = __float2half(f1);
                        const size_t tile = (size_t)((r >> 7) * 16 + (sc >> 6)) * TILE_BYTES;
                        const int idx = (r & 127) * 128 + (sc & 63) * 2;
                        const int sw = idx ^ ((idx >> 3) & 0x70);
                        *(uint32_t*)(D + tile + sw) =
                            ((uint32_t)__half_as_ushort(h1) << 16) | __half_as_ushort(h0);
                    } else {
                        // v: write v^T packed tiles directly (transposed scatter)
                        const int sc = cg - 2048;                  // feature row
                        const size_t tile = (size_t)((sc >> 7) * 64 + (r >> 6)) * TILE_BYTES;
                        const int idx = (sc & 127) * 128 + (r & 63) * 2;
                        const int sw  = idx ^ ((idx >> 3) & 0x70);
                        const int idx2 = idx + 128;                // feature sc+1
                        const int sw2 = idx2 ^ ((idx2 >> 3) & 0x70);
                        *(__half*)((char*)pvt + tile + sw)  = __float2half(f0);
                        *(__half*)((char*)pvt + tile + sw2) = __float2half(f1);
                    }
                } else if (MODE == 1) {
                    const int np = *n_padd_ptr;
                    const float scale = 0.03125f;       // 1/sqrt(1024)
                    float2 o = { v0 * scale, v1 * scale };
                    if (r < np || cg     < np) o.x = NEG_INF_F;
                    if (r < np || cg + 1 < np) o.y = NEG_INF_F;
                    *(float2*)(fout + (size_t)r * T_DIM + cg) = o;
                } else {
                    // PV k-split: accumulate both halves into zeroed out
                    atomicAdd(fout + (size_t)r * C_DIM + cg,     v0);
                    atomicAdd(fout + (size_t)r * C_DIM + cg + 1, v1);
                }
            }
        }
    }
}

// ============================================================================
// Single-pass softmax: one block per row; thread t owns cols [16t, 16t+16).
// Reads fp32 att once, writes packed fp16 tiles, zero-filled to the
// 128-row-block boundary (PV's tile-aligned K range).
// ============================================================================
__global__ __launch_bounds__(256) void softmax_kernel(
    const float* __restrict__ att, char* __restrict__ ath)
{
    const int r = blockIdx.x;
    const float* __restrict__ row = att + (size_t)r * T_DIM;
    const int n = r + 1;
    const int fill_end = ((r >> 7) + 1) << 7;
    const int tid = threadIdx.x;
    const int j0 = tid * 16;
    __shared__ float red[256];

    float x[16];
    #pragma unroll
    for (int g = 0; g < 4; g++) {
        const float4 t = *(const float4*)(row + j0 + g * 4);
        x[g*4+0] = t.x; x[g*4+1] = t.y; x[g*4+2] = t.z; x[g*4+3] = t.w;
    }
    #pragma unroll
    for (int i = 0; i < 16; i++)
        if (j0 + i >= n) x[i] = NEG_INF_F;     // unwritten cols

    float m = x[0];
    #pragma unroll
    for (int i = 1; i < 16; i++) m = fmaxf(m, x[i]);
    red[tid] = m; __syncthreads();
    #pragma unroll
    for (int s = 128; s > 0; s >>= 1) {
        if (tid < s) red[tid] = fmaxf(red[tid], red[tid + s]);
        __syncthreads();
    }
    m = red[0];
    __syncthreads();

    float sum = 0.f;
    #pragma unroll
    for (int i = 0; i < 16; i++) {
        x[i] = __expf(x[i] - m);
        sum += x[i];
    }
    red[tid] = sum; __syncthreads();
    #pragma unroll
    for (int s = 128; s > 0; s >>= 1) {
        if (tid < s) red[tid] += red[tid + s];
        __syncthreads();
    }
    const float inv = 1.0f / red[0];

    if (j0 < fill_end) {
        #pragma unroll
        for (int g = 0; g < 2; g++) {          // two 8-col groups = 16B each
            const int j = j0 + g * 8;
            uint4 uh;
            uint32_t* ph = (uint32_t*)&uh;
            #pragma unroll
            for (int p = 0; p < 4; p++) {
                const __half h0 = __float2half(x[g*8 + p*2]     * inv);
                const __half h1 = __float2half(x[g*8 + p*2 + 1] * inv);
                ph[p] = ((uint32_t)__half_as_ushort(h1) << 16) | __half_as_ushort(h0);
            }
            const size_t tile = (size_t)((r >> 7) * 64 + (j >> 6)) * TILE_BYTES;
            const int idx = (r & 127) * 128 + (j & 63) * 2;
            const int sw = idx ^ ((idx >> 3) & 0x70);
            *(uint4*)(ath + tile + sw) = uh;
        }
    }
}

// ============================================================================
extern "C" void kernel_launch(void* const* d_in, const int* in_sizes, int n_in,
                              void* d_out, int out_size)
{
    const float* x    = (const float*)d_in[0];   // [T, C]
    const float* W    = (const float*)d_in[1];   // [C, 3C]
    const float* bias = (const float*)d_in[2];   // [3C]
    const int* n_padd = (const int*)d_in[3];
    float* out = (float*)d_out;                  // [T, C]

    void* base = nullptr;
    cudaGetSymbolAddress(&base, g_buf);
    char* b = (char*)base;

    float* att  = (float*)(b + OFF_ATT);
    __half* xh  = (__half*)(b + OFF_XH);
    __half* wth = (__half*)(b + OFF_WTH);
    __half* qh  = (__half*)(b + OFF_QH);
    __half* kh  = (__half*)(b + OFF_KH);
    __half* vth = (__half*)(b + OFF_VTH);
    __half* ath = (__half*)(b + OFF_ATH);

    cudaFuncSetAttribute(mm_kernel<0>, cudaFuncAttributeMaxDynamicSharedMemorySize, SMEM_BYTES);
    cudaFuncSetAttribute(mm_kernel<1>, cudaFuncAttributeMaxDynamicSharedMemorySize, SMEM_BYTES);
    cudaFuncSetAttribute(mm_kernel<2>, cudaFuncAttributeMaxDynamicSharedMemorySize, SMEM_BYTES);

    // 0) zero out (PV accumulates atomically)
    cudaMemsetAsync(out, 0, (size_t)T_DIM * C_DIM * sizeof(float));

    // 1) operand prep
    tsplit_kernel<<<dim3(16, 24), 256>>>(W, 3 * C_DIM, wth, 16);   // W^T [3072,1024]
    split_kernel <<<dim3(16, 32), 256>>>(x, xh, 16);               // x   [4096,1024]

    // 2) QKV GEMM (N=64 tiles) -> q/k packed fp16, v^T packed fp16
    mm_kernel<0><<<dim3(48, 32), 256, SMEM_BYTES>>>(
        (const char*)xh, (const char*)wth, 16, nullptr, qh, kh, vth, bias, nullptr);

    // 3) QK GEMM (lower tiles) -> att fp32 (scaled, padding-masked)
    mm_kernel<1><<<dim3(32, 32), 256, SMEM_BYTES>>>(
        (const char*)qh, (const char*)kh, 16, att,
        nullptr, nullptr, nullptr, nullptr, n_padd);

    // 4) softmax -> packed att fp16 tiles (zero-filled to 128 boundary)
    softmax_kernel<<<T_DIM, 256>>>(att, (char*)ath);

    // 5) PV GEMM, k-split2 -> atomicAdd into out
    mm_kernel<2><<<dim3(8, 64), 256, SMEM_BYTES>>>(
        (const char*)ath, (const char*)vth, 64, out,
        nullptr, nullptr, nullptr, nullptr, nullptr);
}

// round 15
// speedup vs baseline: 2.9847x; 1.0007x over previous
#include <cuda_runtime.h>
#include <cuda_fp16.h>
#include <cstdint>
#include <math.h>

#define T_DIM 4096
#define C_DIM 1024
#define NEG_INF_F (-1e30f)

// ============================================================================
// Scratch buffer (single device symbol). 136 MB.
// ============================================================================
#define MB_ (1048576ull)
#define OFF_ATT  (0ull)            // fp32 att     64 MB
#define OFF_XH   (64*MB_)          // x  packed     8 MB
#define OFF_WTH  (72*MB_)          // W^T packed    6 MB
#define OFF_QH   (80*MB_)          // q  packed     8 MB
#define OFF_KH   (88*MB_)          // k  packed     8 MB
#define OFF_VTH  (96*MB_)          // v^T packed    8 MB
#define OFF_ATH  (104*MB_)         // att packed   32 MB
#define BUF_TOTAL (136*MB_)

__device__ __align__(1024) char g_buf[BUF_TOTAL];

// ============================================================================
// Baseline-PTX helpers (sm_80-class only: cp.async, ldmatrix, mma.sync)
// ============================================================================
__device__ __forceinline__ uint32_t smem_u32(const void* p) {
    uint32_t a;
    asm("{ .reg .u64 t; cvta.to.shared.u64 t, %1; cvt.u32.u64 %0, t; }" : "=r"(a) : "l"(p));
    return a;
}
__device__ __forceinline__ void cp16(uint32_t dst, const void* src) {
    asm volatile("cp.async.cg.shared.global [%0], [%1], 16;" :: "r"(dst), "l"(src));
}
#define CP_COMMIT() asm volatile("cp.async.commit_group;" ::: "memory")
#define CP_WAIT1()  asm volatile("cp.async.wait_group 1;" ::: "memory")

#define LDSM_X4(r, addr) \
    asm volatile("ldmatrix.sync.aligned.m8n8.x4.shared.b16 {%0,%1,%2,%3}, [%4];" \
        : "=r"((r)[0]), "=r"((r)[1]), "=r"((r)[2]), "=r"((r)[3]) : "r"(addr))

// fp16 inputs, fp32 accumulators
#define MMA16816(c, a, b0, b1) \
    asm volatile("mma.sync.aligned.m16n8k16.row.col.f32.f16.f16.f32 " \
        "{%0,%1,%2,%3}, {%4,%5,%6,%7}, {%8,%9}, {%0,%1,%2,%3};" \
        : "+f"((c)[0]), "+f"((c)[1]), "+f"((c)[2]), "+f"((c)[3]) \
        : "r"((a)[0]), "r"((a)[1]), "r"((a)[2]), "r"((a)[3]), "r"(b0), "r"(b1))

// ============================================================================
// Packed tile layout: operand [R rows, Ktot cols] K-major fp16 ->
// row-tiles of 128 x 64 cols, 16 KB each, SW128 swizzled, [R/128][Ktot/64].
// ============================================================================
#define TILE_BYTES 16384
#define NSTAGE 3
#define SMEM_BYTES (1024 + NSTAGE * 2 * TILE_BYTES)   // worst case (BN=128)

// Pack fp32 [R, KT*64] into fp16 swizzled tiles (x only).
__global__ void split_kernel(const float* __restrict__ in,
                             __half* __restrict__ dst, int KT)
{
    const int kt = blockIdx.x, rt = blockIdx.y;
    const int ld = KT * 64;
    const float* src = in + (size_t)(rt * 128) * ld + kt * 64;
    char* db = (char*)dst + (size_t)(rt * KT + kt) * TILE_BYTES;
    for (int e = threadIdx.x; e < 8192; e += 256) {
        const int row = e >> 6, col = e & 63;
        const int idx = row * 128 + col * 2;
        const int sw = idx ^ ((idx >> 3) & 0x70);
        *(__half*)(db + sw) = __float2half(src[row * ld + col]);
    }
}

// Transpose-pack: fp32 [Kdim rows, N cols] -> operand [N rows, Kdim] tiles (W only).
__global__ void tsplit_kernel(const float* __restrict__ in, int N,
                              __half* __restrict__ dst, int KT)
{
    const int kt = blockIdx.x, nt = blockIdx.y;
    __shared__ float ts[64][133];
    const float* src = in + (size_t)(kt * 64) * N + nt * 128;
    for (int e = threadIdx.x; e < 8192; e += 256) {
        const int kk = e >> 7, nn = e & 127;
        ts[kk][nn] = src[kk * N + nn];
    }
    __syncthreads();
    char* db = (char*)dst + (size_t)(nt * KT + kt) * TILE_BYTES;
    for (int e = threadIdx.x; e < 8192; e += 256) {
        const int row = e >> 6, col = e & 63;
        const int idx = row * 128 + col * 2;
        const int sw = idx ^ ((idx >> 3) & 0x70);
        *(__half*)(db + sw) = __float2half(ts[col][row]);
    }
}

// ============================================================================
// HMMA GEMM: D[128,BN] fp32 = A * B^T (fp16, fp32 accum), single pass.
// 8 warps (4m x 2n), BK=64, 3-stage cp.async pipeline.
// MODE 0: BN=64.  QKV: cols<2048 -> q/k packed tiles (+bias); cols>=2048 ->
//         v^T packed tiles (+bias), transposed scatter. grid (48, 32).
// MODE 1: BN=128. QK -> att fp32 (scale + padding mask); bx<=by. grid (32,32).
// MODE 2: BN=128. PV k-split2 -> atomicAdd into zeroed out. grid (8, 64);
//         y encodes (row-block, k-half), heavy blocks first.
// ============================================================================
template<int MODE>
__global__ __launch_bounds__(256, 1)
void mm_kernel(const char* __restrict__ Ap, const char* __restrict__ Bp,
               int KT, float* __restrict__ fout,
               __half* __restrict__ pq, __half* __restrict__ pk,
               __half* __restrict__ pvt,
               const float* __restrict__ bias, const int* __restrict__ n_padd_ptr)
{
    constexpr int BN     = (MODE == 0) ? 64 : 128;    // CTA N width
    constexpr int NI     = BN / 16;                   // MMAs per warp in n (8-wide)
    constexpr int NJB    = BN / 32;                   // B ldmatrix.x4 per ks
    constexpr int BBYTES = BN * 128;                  // B stage bytes
    constexpr int STAGE_BYTES = TILE_BYTES + BBYTES;

    extern __shared__ char smem_raw[];
    const int tid = threadIdx.x;
    const int wid = tid >> 5, lane = tid & 31;
    const int wm = wid & 3, wn = wid >> 2;

    const int bx = blockIdx.x;
    int by, total, koff;
    if (MODE == 1) {
        by = blockIdx.y;
        if (bx > by) return;
        total = KT; koff = 0;
    } else if (MODE == 2) {
        const int p = (int)(gridDim.y - 1 - blockIdx.y);  // heavy first
        by = p >> 1;                                      // row-block 0..31
        const int half = p & 1;
        total = by + 1;                                   // k-tiles this job
        koff = half * (by + 1);
    } else {
        by = blockIdx.y;
        total = KT; koff = 0;
    }

    uint32_t sb = smem_u32(smem_raw);
    sb = (sb + 1023u) & ~1023u;

    // ldmatrix swizzled per-lane offsets within a tile/block.
    uint32_t a_off[2][4], b_off[NJB][4];
    #pragma unroll
    for (int mi = 0; mi < 2; mi++)
        #pragma unroll
        for (int ks = 0; ks < 4; ks++) {
            const int row = wm * 32 + mi * 16 + (lane & 15);
            const int col = ks * 16 + ((lane >> 4) << 3);
            const int idx = row * 128 + col * 2;
            a_off[mi][ks] = idx ^ ((idx >> 3) & 0x70);
        }
    #pragma unroll
    for (int nj = 0; nj < NJB; nj++)
        #pragma unroll
        for (int ks = 0; ks < 4; ks++) {
            const int row = wn * (BN / 2) + nj * 16 + (lane & 7) + ((lane >> 4) << 3);
            const int col = ks * 16 + (((lane >> 3) & 1) << 3);
            const int idx = row * 128 + col * 2;
            b_off[nj][ks] = idx ^ ((idx >> 3) & 0x70);
        }

    float acc[2][NI][4];
    #pragma unroll
    for (int mi = 0; mi < 2; mi++)
        #pragma unroll
        for (int ni = 0; ni < NI; ni++)
            #pragma unroll
            for (int e = 0; e < 4; e++) acc[mi][ni][e] = 0.f;

    const char* Ar = Ap + ((size_t)by * KT + koff) * TILE_BYTES;
    const char* Br;
    if (MODE == 0) {
        // B block = 64-row half of a packed 128-row tile
        Br = Bp + (size_t)(bx >> 1) * KT * TILE_BYTES + (size_t)(bx & 1) * 8192;
    } else {
        Br = Bp + ((size_t)bx * KT + koff) * TILE_BYTES;
    }

    auto issue = [&](int kt) {
        const uint32_t st = sb + (kt % NSTAGE) * STAGE_BYTES;
        const size_t toff = (size_t)kt * TILE_BYTES;
        #pragma unroll
        for (int w = 0; w < 4; w++) {
            const int o = w * 4096 + tid * 16;
            cp16(st + o, Ar + toff + o);
        }
        #pragma unroll
        for (int w = 0; w < BBYTES / 4096; w++) {
            const int o = w * 4096 + tid * 16;
            cp16(st + TILE_BYTES + o, Br + toff + o);
        }
        CP_COMMIT();
    };

    issue(0);
    if (total > 1) issue(1);
    else CP_COMMIT();

    for (int i = 0; i < total; i++) {
        CP_WAIT1();
        __syncthreads();
        const uint32_t st = sb + (i % NSTAGE) * STAGE_BYTES;
        const uint32_t stb = st + TILE_BYTES;

        #pragma unroll
        for (int ks = 0; ks < 4; ks++) {
            uint32_t afr[2][4], bfr[NJB][4];
            #pragma unroll
            for (int mi = 0; mi < 2; mi++) LDSM_X4(afr[mi], st + a_off[mi][ks]);
            #pragma unroll
            for (int nj = 0; nj < NJB; nj++) LDSM_X4(bfr[nj], stb + b_off[nj][ks]);
            #pragma unroll
            for (int mi = 0; mi < 2; mi++)
                #pragma unroll
                for (int ni = 0; ni < NI; ni++)
                    MMA16816(acc[mi][ni], afr[mi],
                             bfr[ni >> 1][(ni & 1) * 2],
                             bfr[ni >> 1][(ni & 1) * 2 + 1]);
        }

        if (i + 2 < total) issue(i + 2);
        else CP_COMMIT();           // empty group keeps wait accounting valid
    }

    // ---- epilogue ----
    const int qr = lane >> 2;
    const int qc = (lane & 3) * 2;

    #pragma unroll
    for (int mi = 0; mi < 2; mi++) {
        #pragma unroll
        for (int hf = 0; hf < 2; hf++) {
            const int r = by * 128 + wm * 32 + mi * 16 + qr + hf * 8;
            #pragma unroll
            for (int ni = 0; ni < NI; ni++) {
                const int cg = bx * BN + wn * (BN / 2) + ni * 8 + qc;
                const float v0 = acc[mi][ni][hf * 2];
                const float v1 = acc[mi][ni][hf * 2 + 1];
                if (MODE == 0) {
                    const float f0 = v0 + bias[cg];
                    const float f1 = v1 + bias[cg + 1];
                    if (cg < 2048) {
                        // q (sec 0) / k (sec 1): packed fp16 swizzled tiles
                        const int sec = cg >> 10;
                        const int sc = cg & 1023;
                        char* D = (char*)(sec ? pk : pq);
                        const __half h0 = __float2half(f0);
                        const __half h1 = __float2half(f1);
                        const size_t tile = (size_t)((r >> 7) * 16 + (sc >> 6)) * TILE_BYTES;
                        const int idx = (r & 127) * 128 + (sc & 63) * 2;
                        const int sw = idx ^ ((idx >> 3) & 0x70);
                        *(uint32_t*)(D + tile + sw) =
                            ((uint32_t)__half_as_ushort(h1) << 16) | __half_as_ushort(h0);
                    } else {
                        // v: write v^T packed tiles directly (transposed scatter)
                        const int sc = cg - 2048;                  // feature row
                        const size_t tile = (size_t)((sc >> 7) * 64 + (r >> 6)) * TILE_BYTES;
                        const int idx = (sc & 127) * 128 + (r & 63) * 2;
                        const int sw  = idx ^ ((idx >> 3) & 0x70);
                        const int idx2 = idx + 128;                // feature sc+1
                        const int sw2 = idx2 ^ ((idx2 >> 3) & 0x70);
                        *(__half*)((char*)pvt + tile + sw)  = __float2half(f0);
                        *(__half*)((char*)pvt + tile + sw2) = __float2half(f1);
                    }
                } else if (MODE == 1) {
                    const int np = *n_padd_ptr;
                    const float scale = 0.03125f;       // 1/sqrt(1024)
                    float2 o = { v0 * scale, v1 * scale };
                    if (r < np || cg     < np) o.x = NEG_INF_F;
                    if (r < np || cg + 1 < np) o.y = NEG_INF_F;
                    *(float2*)(fout + (size_t)r * T_DIM + cg) = o;
                } else {
                    // PV k-split: accumulate both halves into zeroed out
                    atomicAdd(fout + (size_t)r * C_DIM + cg,     v0);
                    atomicAdd(fout + (size_t)r * C_DIM + cg + 1, v1);
                }
            }
        }
    }
}

// ============================================================================
// Single-pass softmax: one block per row; thread t owns cols [16t, 16t+16).
// Reads fp32 att once, writes packed fp16 tiles, zero-filled to the
// 128-row-block boundary (PV's tile-aligned K range).
// ============================================================================
__global__ __launch_bounds__(256) void softmax_kernel(
    const float* __restrict__ att, char* __restrict__ ath)
{
    const int r = blockIdx.x;
    const float* __restrict__ row = att + (size_t)r * T_DIM;
    const int n = r + 1;
    const int fill_end = ((r >> 7) + 1) << 7;
    const int tid = threadIdx.x;
    const int j0 = tid * 16;
    __shared__ float red[256];

    float x[16];
    #pragma unroll
    for (int g = 0; g < 4; g++) {
        const float4 t = *(const float4*)(row + j0 + g * 4);
        x[g*4+0] = t.x; x[g*4+1] = t.y; x[g*4+2] = t.z; x[g*4+3] = t.w;
    }
    #pragma unroll
    for (int i = 0; i < 16; i++)
        if (j0 + i >= n) x[i] = NEG_INF_F;     // unwritten cols

    float m = x[0];
    #pragma unroll
    for (int i = 1; i < 16; i++) m = fmaxf(m, x[i]);
    red[tid] = m; __syncthreads();
    #pragma unroll
    for (int s = 128; s > 0; s >>= 1) {
        if (tid < s) red[tid] = fmaxf(red[tid], red[tid + s]);
        __syncthreads();
    }
    m = red[0];
    __syncthreads();

    float sum = 0.f;
    #pragma unroll
    for (int i = 0; i < 16; i++) {
        x[i] = __expf(x[i] - m);
        sum += x[i];
    }
    red[tid] = sum; __syncthreads();
    #pragma unroll
    for (int s = 128; s > 0; s >>= 1) {
        if (tid < s) red[tid] += red[tid + s];
        __syncthreads();
    }
    const float inv = 1.0f / red[0];

    if (j0 < fill_end) {
        #pragma unroll
        for (int g = 0; g < 2; g++) {          // two 8-col groups = 16B each
            const int j = j0 + g * 8;
            uint4 uh;
            uint32_t* ph = (uint32_t*)&uh;
            #pragma unroll
            for (int p = 0; p < 4; p++) {
                const __half h0 = __float2half(x[g*8 + p*2]     * inv);
                const __half h1 = __float2half(x[g*8 + p*2 + 1] * inv);
                ph[p] = ((uint32_t)__half_as_ushort(h1) << 16) | __half_as_ushort(h0);
            }
            const size_t tile = (size_t)((r >> 7) * 64 + (j >> 6)) * TILE_BYTES;
            const int idx = (r & 127) * 128 + (j & 63) * 2;
            const int sw = idx ^ ((idx >> 3) & 0x70);
            *(uint4*)(ath + tile + sw) = uh;
        }
    }
}

// ============================================================================
extern "C" void kernel_launch(void* const* d_in, const int* in_sizes, int n_in,
                              void* d_out, int out_size)
{
    const float* x    = (const float*)d_in[0];   // [T, C]
    const float* W    = (const float*)d_in[1];   // [C, 3C]
    const float* bias = (const float*)d_in[2];   // [3C]
    const int* n_padd = (const int*)d_in[3];
    float* out = (float*)d_out;                  // [T, C]

    void* base = nullptr;
    cudaGetSymbolAddress(&base, g_buf);
    char* b = (char*)base;

    float* att  = (float*)(b + OFF_ATT);
    __half* xh  = (__half*)(b + OFF_XH);
    __half* wth = (__half*)(b + OFF_WTH);
    __half* qh  = (__half*)(b + OFF_QH);
    __half* kh  = (__half*)(b + OFF_KH);
    __half* vth = (__half*)(b + OFF_VTH);
    __half* ath = (__half*)(b + OFF_ATH);

    cudaFuncSetAttribute(mm_kernel<0>, cudaFuncAttributeMaxDynamicSharedMemorySize, SMEM_BYTES);
    cudaFuncSetAttribute(mm_kernel<1>, cudaFuncAttributeMaxDynamicSharedMemorySize, SMEM_BYTES);
    cudaFuncSetAttribute(mm_kernel<2>, cudaFuncAttributeMaxDynamicSharedMemorySize, SMEM_BYTES);

    // 0) zero out (PV accumulates atomically)
    cudaMemsetAsync(out, 0, (size_t)T_DIM * C_DIM * sizeof(float));

    // 1) operand prep
    tsplit_kernel<<<dim3(16, 24), 256>>>(W, 3 * C_DIM, wth, 16);   // W^T [3072,1024]
    split_kernel <<<dim3(16, 32), 256>>>(x, xh, 16);               // x   [4096,1024]

    // 2) QKV GEMM (N=64 tiles) -> q/k packed fp16, v^T packed fp16
    mm_kernel<0><<<dim3(48, 32), 256, SMEM_BYTES>>>(
        (const char*)xh, (const char*)wth, 16, nullptr, qh, kh, vth, bias, nullptr);

    // 3) QK GEMM (lower tiles) -> att fp32 (scaled, padding-masked)
    mm_kernel<1><<<dim3(32, 32), 256, SMEM_BYTES>>>(
        (const char*)qh, (const char*)kh, 16, att,
        nullptr, nullptr, nullptr, nullptr, n_padd);

    // 4) softmax -> packed att fp16 tiles (zero-filled to 128 boundary)
    softmax_kernel<<<T_DIM, 256>>>(att, (char*)ath);

    // 5) PV GEMM, k-split2 -> atomicAdd into out
    mm_kernel<2><<<dim3(8, 64), 256, SMEM_BYTES>>>(
        (const char*)ath, (const char*)vth, 64, out,
        nullptr, nullptr, nullptr, nullptr, nullptr);
}